// round 13
// baseline (speedup 1.0000x reference)
#include <cuda_runtime.h>
#include <cstdint>

#define NW 14
#define NSTATE (1 << NW)        // 16384 amplitudes
#define NLAYERS 6               // (DEPTH+1) * SEL_LAYERS
#define NTHREADS 512
#define NWARPS (NTHREADS / 32)
#define NPARAMS (2 * NW * 3)    // 84

// ---------------------------------------------------------------------------
// Compile-time GF(2) algebra: lazy CNOT permutation tracking.
// psi[x] = a[T*x]; Rot on wire w pairs (j, j^v), v = col_w(T); role parity =
// <row_w(Tinv), j>.  Storage swizzle sw(j)=j^(j>>4)^(j>>9) (linear).
// Per layer: wires partitioned (A[5], B[5], C[4]) chosen at compile time so
// that both halves of the warp-private super-sweep have rank-4 bank-pair
// lane images (2-phase LDS.64/STS.64).  A warp owns one 1024-amp coset of
// span{A,B}; groups A and B sync with __syncwarp only.  12 full barriers.
// Measurement fused into the final C sweep via 4-dim Walsh-Hadamard.
// ---------------------------------------------------------------------------

struct LayerTab {
    uint16_t v[NW];      // T columns for this layer
    uint16_t umask[NW];  // Tinv rows (role-parity masks)
    uint8_t  uidx[NW];   // gate matrix index: (L&1)*NW + w
};
struct AllTabs {
    LayerTab lay[NLAYERS];
    uint16_t zu[NW];     // final Tinv rows -> measurement sign masks
};

__host__ __device__ constexpr unsigned swz(unsigned j) {
    return j ^ (j >> 4) ^ (j >> 9);
}

__host__ __device__ constexpr AllTabs build_all() {
    AllTabs t{};
    uint16_t Tcol[NW]  = {};
    uint16_t TiRow[NW] = {};
    for (int i = 0; i < NW; i++) { Tcol[i] = (uint16_t)(1u << i); TiRow[i] = (uint16_t)(1u << i); }

    for (int L = 0; L < NLAYERS; L++) {
        LayerTab& lt = t.lay[L];
        for (int w = 0; w < NW; w++) {
            lt.v[w]     = Tcol[w];
            lt.umask[w] = TiRow[w];
            lt.uidx[w]  = (uint8_t)((L & 1) * NW + w);
        }
        int r = (L & 1) + 1;
        uint16_t Qrow[NW]  = {};
        uint16_t QiRow[NW] = {};
        for (int i = 0; i < NW; i++) { Qrow[i] = (uint16_t)(1u << i); QiRow[i] = (uint16_t)(1u << i); }
        for (int w = NW - 1; w >= 0; w--) Qrow[(w + r) % NW]  = (uint16_t)(Qrow[(w + r) % NW]  ^ Qrow[w]);
        for (int w = 0; w < NW; w++)      QiRow[(w + r) % NW] = (uint16_t)(QiRow[(w + r) % NW] ^ QiRow[w]);
        uint16_t nT[NW]  = {};
        uint16_t nTi[NW] = {};
        for (int w = 0; w < NW; w++) {
            uint16_t c = 0;
            for (int i = 0; i < NW; i++) if ((Qrow[i] >> w) & 1) c = (uint16_t)(c ^ Tcol[i]);
            nT[w] = c;
        }
        for (int i = 0; i < NW; i++) {
            uint16_t rr = 0;
            for (int k = 0; k < NW; k++) if ((QiRow[i] >> k) & 1) rr = (uint16_t)(rr ^ TiRow[k]);
            nTi[i] = rr;
        }
        for (int i = 0; i < NW; i++) { Tcol[i] = nT[i]; TiRow[i] = nTi[i]; }
    }
    for (int i = 0; i < NW; i++) t.zu[i] = TiRow[i];
    return t;
}

// Candidate vectors for complement-basis greedy: 14 units + 91 pairs.
__host__ __device__ constexpr uint16_t cand_vec(int idx) {
    if (idx < 14) return (uint16_t)(1u << idx);
    int k = idx - 14;
    for (int a = 0; a < 14; a++) {
        int cnt = 13 - a;
        if (k < cnt) return (uint16_t)((1u << a) | (1u << (a + 1 + k)));
        k -= cnt;
    }
    return 1;
}
#define NCAND (14 + 91)

// ---------------------------------------------------------------------------
// Per-layer wire partition (A[5], B[5], C[4]) with bank-rank guarantees.
// ---------------------------------------------------------------------------
struct Part { int A[5]; int B[5]; int C[4]; };

__host__ __device__ constexpr Part choose_part(int L) {
    AllTabs t = build_all();
    Part p{};
    const int starts[14] = {10, 0, 1, 2, 3, 4, 5, 6, 7, 8, 9, 11, 12, 13};
    for (int si = 0; si < 14; si++) {
        int s = starts[si];
        int C[4] = {s, (s + 1) % 14, (s + 2) % 14, (s + 3) % 14};
        bool inC[14] = {};
        for (int i = 0; i < 4; i++) inC[C[i]] = true;
        int rem[10] = {}; int nr = 0;
        for (int wv = 0; wv < 14; wv++) if (!inC[wv]) rem[nr++] = wv;
        uint16_t img[10] = {};
        for (int i = 0; i < 10; i++) img[i] = (uint16_t)(swz(t.lay[L].v[rem[i]]) & 15u);
        for (int i0 = 0; i0 < 6; i0++)
        for (int i1 = i0 + 1; i1 < 7; i1++)
        for (int i2 = i1 + 1; i2 < 8; i2++)
        for (int i3 = i2 + 1; i3 < 9; i3++)
        for (int i4 = i3 + 1; i4 < 10; i4++) {
            bool inB[10] = {};
            inB[i0] = true; inB[i1] = true; inB[i2] = true; inB[i3] = true; inB[i4] = true;
            uint16_t e[4] = {}; int r = 0;
            for (int k = 0; k < 10; k++) if (inB[k]) {
                uint16_t x = img[k];
                for (int b = 3; b >= 0; b--) if (((x >> b) & 1) && e[b]) x = (uint16_t)(x ^ e[b]);
                if (x) { int b = 3; while (!((x >> b) & 1)) b--; e[b] = x; r++; }
            }
            if (r != 4) continue;
            uint16_t e2[4] = {}; int r2 = 0;
            for (int k = 0; k < 10; k++) if (!inB[k]) {
                uint16_t x = img[k];
                for (int b = 3; b >= 0; b--) if (((x >> b) & 1) && e2[b]) x = (uint16_t)(x ^ e2[b]);
                if (x) { int b = 3; while (!((x >> b) & 1)) b--; e2[b] = x; r2++; }
            }
            if (r2 != 4) continue;
            int ai = 0, bi = 0;
            for (int k = 0; k < 10; k++) { if (inB[k]) p.B[bi++] = rem[k]; else p.A[ai++] = rem[k]; }
            for (int i = 0; i < 4; i++) p.C[i] = C[i];
            return p;
        }
    }
    for (int i = 0; i < 5; i++) { p.A[i] = i; p.B[i] = 5 + i; }
    for (int i = 0; i < 4; i++) p.C[i] = 10 + i;
    return p;
}

// ---------------------------------------------------------------------------
// Super-sweep half tables (gates = one 5-group; lanes enumerate the other).
// ---------------------------------------------------------------------------
struct SSTab {
    uint16_t offs[32];   // pre-swizzled xor-offsets over the gate span
    uint16_t umask[5];   // role-parity masks of the gates
    uint8_t  uidx[5];    // gate matrix indices
    uint16_t vlane[5];   // raw lane-enumeration vectors (other group's v)
    uint16_t cw[4];      // raw complement basis of span{A,B} (warp bits)
};

__host__ __device__ constexpr SSTab make_ssgrp(int L, int half) {
    AllTabs t = build_all();
    Part p = choose_part(L);
    const int* Wg = (half == 0) ? p.A : p.B;   // gate wires
    const int* Wl = (half == 0) ? p.B : p.A;   // lane wires
    SSTab s{};
    for (int i = 0; i < 5; i++) {
        s.umask[i] = t.lay[L].umask[Wg[i]];
        s.uidx[i]  = t.lay[L].uidx[Wg[i]];
        s.vlane[i] = t.lay[L].v[Wl[i]];
    }
    for (int m = 0; m < 32; m++) {
        uint16_t x = 0;
        for (int i = 0; i < 5; i++) if ((m >> i) & 1) x = (uint16_t)(x ^ t.lay[L].v[Wg[i]]);
        s.offs[m] = (uint16_t)swz(x);
    }
    // complement basis of the 10-dim span{A,B} (warp-level, no bank constraint)
    uint16_t ech[14] = {};
    for (int i = 0; i < 10; i++) {
        uint16_t x = t.lay[L].v[p.A[i < 5 ? i : 0]];
        x = (i < 5) ? t.lay[L].v[p.A[i]] : t.lay[L].v[p.B[i - 5]];
        for (int b = 13; b >= 0; b--) if (((x >> b) & 1) && ech[b]) x = (uint16_t)(x ^ ech[b]);
        if (x) { int b = 13; while (!((x >> b) & 1)) b--; ech[b] = x; }
    }
    int got = 0;
    for (int ci = 0; ci < NCAND && got < 4; ci++) {
        uint16_t x0 = cand_vec(ci), x = x0;
        for (int b = 13; b >= 0; b--) if (((x >> b) & 1) && ech[b]) x = (uint16_t)(x ^ ech[b]);
        if (!x) continue;
        { int b = 13; while (!((x >> b) & 1)) b--; ech[b] = x; }
        s.cw[got++] = x0;
    }
    for (int i = got; i < 4; i++) s.cw[i] = 0;
    return s;
}

// ---------------------------------------------------------------------------
// C-group sweep tables (G=4, free complement basis, bank-greedy first 4).
// ---------------------------------------------------------------------------
struct SweepTab {
    uint16_t offs[16];
    uint16_t umask[4];
    uint8_t  uidx[4];
    uint16_t w[10];
};

__host__ __device__ constexpr SweepTab make_sweepC(int L) {
    AllTabs t = build_all();
    Part p = choose_part(L);
    SweepTab s{};
    for (int i = 0; i < 4; i++) { s.umask[i] = t.lay[L].umask[p.C[i]]; s.uidx[i] = t.lay[L].uidx[p.C[i]]; }
    for (int m = 0; m < 16; m++) {
        uint16_t x = 0;
        for (int i = 0; i < 4; i++) if ((m >> i) & 1) x = (uint16_t)(x ^ t.lay[L].v[p.C[i]]);
        s.offs[m] = (uint16_t)swz(x);
    }
    uint16_t ech[14] = {};
    for (int i = 0; i < 4; i++) {
        uint16_t x = t.lay[L].v[p.C[i]];
        for (int b = 13; b >= 0; b--) if (((x >> b) & 1) && ech[b]) x = (uint16_t)(x ^ ech[b]);
        if (x) { int b = 13; while (!((x >> b) & 1)) b--; ech[b] = x; }
    }
    uint16_t bech[4] = {};
    for (int i = 0; i < 10; i++) {
        uint16_t pick = 0; bool found = false; bool bankok = false;
        for (int ci = 0; ci < NCAND && !found; ci++) {
            uint16_t x0 = cand_vec(ci), x = x0;
            for (int b = 13; b >= 0; b--) if (((x >> b) & 1) && ech[b]) x = (uint16_t)(x ^ ech[b]);
            if (!x) continue;
            if (i < 4) {
                uint16_t im = (uint16_t)(swz(x0) & 15u);
                for (int b = 3; b >= 0; b--) if (((im >> b) & 1) && bech[b]) im = (uint16_t)(im ^ bech[b]);
                if (!im) continue;
            }
            pick = x0; found = true; bankok = true;
        }
        for (int ci = 0; ci < NCAND && !found; ci++) {
            uint16_t x0 = cand_vec(ci), x = x0;
            for (int b = 13; b >= 0; b--) if (((x >> b) & 1) && ech[b]) x = (uint16_t)(x ^ ech[b]);
            if (!x) continue;
            pick = x0; found = true; bankok = false;
        }
        {
            uint16_t x = pick;
            for (int b = 13; b >= 0; b--) if (((x >> b) & 1) && ech[b]) x = (uint16_t)(x ^ ech[b]);
            if (x) { int b = 13; while (!((x >> b) & 1)) b--; ech[b] = x; }
        }
        if (i < 4 && bankok) {
            uint16_t im = (uint16_t)(swz(pick) & 15u);
            for (int b = 3; b >= 0; b--) if (((im >> b) & 1) && bech[b]) im = (uint16_t)(im ^ bech[b]);
            if (im) { int b = 3; while (!((im >> b) & 1)) b--; bech[b] = im; }
        }
        s.w[i] = pick;
    }
    return s;
}

// Measurement tables for the fused final C sweep of layer 5.
struct MeasTab {
    uint8_t  twalsh[NW];
    uint16_t zu[NW];
};
__host__ __device__ constexpr MeasTab make_meas() {
    AllTabs t = build_all();
    Part p = choose_part(5);
    MeasTab m{};
    for (int w = 0; w < NW; w++) {
        m.zu[w] = t.zu[w];
        unsigned k = 0;
        for (int i = 0; i < 4; i++) {
            unsigned pr = (unsigned)(t.lay[5].v[p.C[i]] & t.zu[w]);
            int pc = 0;
            for (int b = 0; b < 16; b++) pc += (pr >> b) & 1;
            k |= (unsigned)(pc & 1) << i;
        }
        m.twalsh[w] = (uint8_t)k;
    }
    return m;
}

// ---------------------------------------------------------------------------
// Packed f32x2 complex helpers. Amplitude packed as u64: lo=re, hi=im.
// ---------------------------------------------------------------------------
typedef unsigned long long u64;

__device__ __forceinline__ u64 pk(float lo, float hi) {
    u64 r; asm("mov.b64 %0, {%1,%2};" : "=l"(r) : "f"(lo), "f"(hi)); return r;
}
__device__ __forceinline__ u64 sw64(u64 a) {
    unsigned lo, hi;
    asm("mov.b64 {%0,%1}, %2;" : "=r"(lo), "=r"(hi) : "l"(a));
    u64 r; asm("mov.b64 %0, {%1,%2};" : "=l"(r) : "r"(hi), "r"(lo)); return r;
}
__device__ __forceinline__ u64 fma2_(u64 a, u64 b, u64 c) {
    u64 d; asm("fma.rn.f32x2 %0, %1, %2, %3;" : "=l"(d) : "l"(a), "l"(b), "l"(c)); return d;
}
__device__ __forceinline__ u64 mul2_(u64 a, u64 b) {
    u64 d; asm("mul.rn.f32x2 %0, %1, %2;" : "=l"(d) : "l"(a), "l"(b)); return d;
}

#define SGNC 0x8000000080000000ULL
#define ONEC 0x000000003F800000ULL   // pk(1.0f, 0.0f)

// ---------------------------------------------------------------------------
// Warp-private super-sweep half: 5 gates on the warp's 1024-amp block.
// ---------------------------------------------------------------------------
template <int L, int half, bool INIT>
__device__ __forceinline__ void ss_half(u64* __restrict__ st,
                                        const u64* __restrict__ Us,
                                        unsigned sj0) {
    constexpr SSTab tb = make_ssgrp(L, half);
    const unsigned lane = threadIdx.x & 31u, wp = threadIdx.x >> 5;
    unsigned rep = 0;
#pragma unroll
    for (int i = 0; i < 4; i++) rep ^= (wp & (1u << i)) ? (unsigned)tb.cw[i] : 0u;
#pragma unroll
    for (int i = 0; i < 5; i++) rep ^= (lane & (1u << i)) ? (unsigned)tb.vlane[i] : 0u;
    unsigned sj = swz(rep);
    u64 a[32];
    if (INIT) {
#pragma unroll
        for (int m = 0; m < 32; m++)
            a[m] = ((sj ^ (unsigned)tb.offs[m]) == sj0) ? ONEC : 0ULL;
    } else {
#pragma unroll
        for (int m = 0; m < 32; m++) a[m] = st[sj ^ (unsigned)tb.offs[m]];
    }
#pragma unroll
    for (int i = 0; i < 5; i++) {
        const u64* Ub = Us + (int)tb.uidx[i] * 4;        // broadcast LDS
        u64 bb   = (u64)(__popc(rep & (unsigned)tb.umask[i]) & 1u);
        u64 mask = (0ULL - bb) & SGNC;
        u64 A  = Ub[0];
        u64 B  = Ub[1] ^ mask;
        u64 Bn = B ^ SGNC;
        u64 C  = Ub[2] ^ mask;
        u64 Cn = C ^ SGNC;
        u64 D  = Ub[3];
#pragma unroll
        for (int m = 0; m < 32; m++) {
            if (m & (1 << i)) continue;
            u64 a0 = a[m], a1 = a[m | (1 << i)];
            u64 a0s = sw64(a0), a1s = sw64(a1);
            a[m]            = fma2_(A, a0, fma2_(B,  a0s, fma2_(C,  a1, mul2_(D, a1s))));
            a[m | (1 << i)] = fma2_(A, a1, fma2_(Bn, a1s, fma2_(Cn, a0, mul2_(D, a0s))));
        }
    }
#pragma unroll
    for (int m = 0; m < 32; m++) st[sj ^ (unsigned)tb.offs[m]] = a[m];
}

// C-group sweep (G=4, 2 cosets/thread, pipelined load-compute-store).
template <int L>
__device__ __forceinline__ void sweepC(u64* __restrict__ st,
                                       const u64* __restrict__ Us) {
    constexpr SweepTab tb = make_sweepC(L);
    constexpr int NITER = 2;
    unsigned rep[NITER], sj[NITER];
    u64 a[NITER][16];
#pragma unroll
    for (int kk = 0; kk < NITER; kk++) {
        unsigned c = threadIdx.x + kk * NTHREADS;
        unsigned r = 0;
#pragma unroll
        for (int i = 0; i < 10; i++)
            r ^= (c & (1u << i)) ? (unsigned)tb.w[i] : 0u;
        rep[kk] = r; sj[kk] = swz(r);
#pragma unroll
        for (int m = 0; m < 16; m++) a[kk][m] = st[sj[kk] ^ (unsigned)tb.offs[m]];
    }
#pragma unroll
    for (int i = 0; i < 4; i++) {
        const u64* Ub = Us + (int)tb.uidx[i] * 4;
        u64 u0 = Ub[0], u1 = Ub[1], u2 = Ub[2], u3 = Ub[3];
#pragma unroll
        for (int kk = 0; kk < NITER; kk++) {
            u64 bb   = (u64)(__popc(rep[kk] & (unsigned)tb.umask[i]) & 1u);
            u64 mask = (0ULL - bb) & SGNC;
            u64 A  = u0;
            u64 B  = u1 ^ mask;
            u64 Bn = B ^ SGNC;
            u64 C  = u2 ^ mask;
            u64 Cn = C ^ SGNC;
            u64 D  = u3;
#pragma unroll
            for (int m = 0; m < 16; m++) {
                if (m & (1 << i)) continue;
                u64 a0 = a[kk][m], a1 = a[kk][m | (1 << i)];
                u64 a0s = sw64(a0), a1s = sw64(a1);
                a[kk][m]            = fma2_(A, a0, fma2_(B,  a0s, fma2_(C,  a1, mul2_(D, a1s))));
                a[kk][m | (1 << i)] = fma2_(A, a1, fma2_(Bn, a1s, fma2_(Cn, a0, mul2_(D, a0s))));
            }
        }
    }
#pragma unroll
    for (int kk = 0; kk < NITER; kk++)
#pragma unroll
        for (int m = 0; m < 16; m++) st[sj[kk] ^ (unsigned)tb.offs[m]] = a[kk][m];
}

// Final C sweep (layer 5) fused with |psi|^2 measurement (no stores).
__device__ __forceinline__ void sweep_final(const u64* __restrict__ st,
                                            const u64* __restrict__ Us,
                                            float* __restrict__ acc) {
    constexpr SweepTab tb = make_sweepC(5);
    constexpr MeasTab  mt = make_meas();
    constexpr int NITER = 2;
    unsigned rep[NITER], sj[NITER];
    u64 a[NITER][16];
#pragma unroll
    for (int kk = 0; kk < NITER; kk++) {
        unsigned c = threadIdx.x + kk * NTHREADS;
        unsigned r = 0;
#pragma unroll
        for (int i = 0; i < 10; i++)
            r ^= (c & (1u << i)) ? (unsigned)tb.w[i] : 0u;
        rep[kk] = r; sj[kk] = swz(r);
#pragma unroll
        for (int m = 0; m < 16; m++) a[kk][m] = st[sj[kk] ^ (unsigned)tb.offs[m]];
    }
#pragma unroll
    for (int i = 0; i < 4; i++) {
        const u64* Ub = Us + (int)tb.uidx[i] * 4;
        u64 u0 = Ub[0], u1 = Ub[1], u2 = Ub[2], u3 = Ub[3];
#pragma unroll
        for (int kk = 0; kk < NITER; kk++) {
            u64 bb   = (u64)(__popc(rep[kk] & (unsigned)tb.umask[i]) & 1u);
            u64 mask = (0ULL - bb) & SGNC;
            u64 A  = u0;
            u64 B  = u1 ^ mask;
            u64 Bn = B ^ SGNC;
            u64 C  = u2 ^ mask;
            u64 Cn = C ^ SGNC;
            u64 D  = u3;
#pragma unroll
            for (int m = 0; m < 16; m++) {
                if (m & (1 << i)) continue;
                u64 a0 = a[kk][m], a1 = a[kk][m | (1 << i)];
                u64 a0s = sw64(a0), a1s = sw64(a1);
                a[kk][m]            = fma2_(A, a0, fma2_(B,  a0s, fma2_(C,  a1, mul2_(D, a1s))));
                a[kk][m | (1 << i)] = fma2_(A, a1, fma2_(Bn, a1s, fma2_(Cn, a0, mul2_(D, a0s))));
            }
        }
    }
#pragma unroll
    for (int kk = 0; kk < NITER; kk++) {
        float pv[16];
#pragma unroll
        for (int m = 0; m < 16; m++) {
            float ax = __uint_as_float((unsigned)a[kk][m]);
            float ay = __uint_as_float((unsigned)(a[kk][m] >> 32));
            pv[m] = ax * ax + ay * ay;
        }
#pragma unroll
        for (int i = 0; i < 4; i++) {
#pragma unroll
            for (int m = 0; m < 16; m++) {
                if (m & (1 << i)) continue;
                float x = pv[m], y = pv[m | (1 << i)];
                pv[m] = x + y; pv[m | (1 << i)] = x - y;
            }
        }
#pragma unroll
        for (int w = 0; w < NW; w++) {
            unsigned bs = (__popc(rep[kk] & (unsigned)mt.zu[w]) & 1u) << 31;
            acc[w] += __uint_as_float(__float_as_uint(pv[mt.twalsh[w]]) ^ bs);
        }
    }
}

template <int L>
__device__ __forceinline__ void layer(u64* __restrict__ st, const u64* __restrict__ Us) {
    ss_half<L, 0, false>(st, Us, 0u);
    __syncwarp(0xffffffffu);
    ss_half<L, 1, false>(st, Us, 0u);
    __syncthreads();
    sweepC<L>(st, Us);
    __syncthreads();
}

__global__ void __launch_bounds__(NTHREADS, 1)
qsim_kernel(const float* __restrict__ state_batch,
            const float* __restrict__ params,
            const float* __restrict__ head_w,
            const float* __restrict__ head_b,
            float* __restrict__ out) {
    extern __shared__ u64 st[];                    // 16384 x 8B = 128 KB
    __shared__ u64   Usm[2 * NW * 4];              // 28 gates x {u_rr,u_pm,v_rr,v_pm}
    __shared__ float redsm[NWARPS * NW];

    const int b   = blockIdx.x;
    const int tid = threadIdx.x;

    // 28 distinct Rot matrices (weights shared across the 3 blocks).
    if (tid < 2 * NW) {
        const float* p = params + (size_t)b * NPARAMS + tid * 3;
        float phi = p[0], th = p[1], om = p[2];
        float s, c;  sincosf(0.5f * th, &s, &c);
        float sa, ca; sincosf(0.5f * (phi + om), &sa, &ca);
        float sb, cb; sincosf(0.5f * (phi - om), &sb, &cb);
        float ur =  ca * c, ui = -sa * c;
        float vr = -cb * s, vi = -sb * s;
        u64* U = &Usm[tid * 4];
        U[0] = pk( ur, ur);     // u_rr
        U[1] = pk(-ui, ui);     // u_pm
        U[2] = pk( vr, vr);     // v_rr
        U[3] = pk(-vi, vi);     // v_pm
    }

    // AngleEmbedding: RX(0 or pi) -> basis state j0 (global phase irrelevant).
    unsigned j0 = 0;
    {
        const float* sb_ = state_batch + (size_t)b * (NSTATE * 2);
#pragma unroll
        for (int w = 0; w < NW; w++) if (sb_[w] < 0.f) j0 |= (1u << w);
    }
    const unsigned sj0 = swz(j0);
    __syncthreads();                                // Usm ready

    // Layer 0: A-half initializes from the basis delta (no load / zero pass).
    ss_half<0, 0, true>(st, Usm, sj0);
    __syncwarp(0xffffffffu);
    ss_half<0, 1, false>(st, Usm, 0u);
    __syncthreads();
    sweepC<0>(st, Usm);
    __syncthreads();
    layer<1>(st, Usm);
    layer<2>(st, Usm);
    layer<3>(st, Usm);
    layer<4>(st, Usm);
    // Layer 5: super-sweep, then C sweep fused with measurement.
    ss_half<5, 0, false>(st, Usm, 0u);
    __syncwarp(0xffffffffu);
    ss_half<5, 1, false>(st, Usm, 0u);
    __syncthreads();

    float acc[NW];
#pragma unroll
    for (int w = 0; w < NW; w++) acc[w] = 0.f;
    sweep_final(st, Usm, acc);

    // Block-reduce acc and apply linear head
#pragma unroll
    for (int w = 0; w < NW; w++) {
#pragma unroll
        for (int o = 16; o > 0; o >>= 1) acc[w] += __shfl_xor_sync(0xffffffffu, acc[w], o);
    }
    const int lane = tid & 31, warp = tid >> 5;
    if (lane == 0) {
#pragma unroll
        for (int w = 0; w < NW; w++) redsm[warp * NW + w] = acc[w];
    }
    __syncthreads();
    if (warp == 0 && lane < NW) {
        float z = 0.f;
#pragma unroll
        for (int k = 0; k < NWARPS; k++) z += redsm[k * NW + lane];
        redsm[lane] = z * head_w[lane];
    }
    __syncthreads();
    if (tid == 0) {
        float r_ = head_b[0];
#pragma unroll
        for (int w = 0; w < NW; w++) r_ += redsm[w];
        out[b] = r_;
    }
}

extern "C" void kernel_launch(void* const* d_in, const int* in_sizes, int n_in,
                              void* d_out, int out_size) {
    const float* state_batch = (const float*)d_in[0];
    const float* params      = (const float*)d_in[1];
    const float* head_w      = (const float*)d_in[2];
    const float* head_b      = (const float*)d_in[3];
    float* out = (float*)d_out;

    int B = in_sizes[0] / (NSTATE * 2);   // 512
    cudaFuncSetAttribute(qsim_kernel, cudaFuncAttributeMaxDynamicSharedMemorySize,
                         NSTATE * (int)sizeof(u64));
    qsim_kernel<<<B, NTHREADS, NSTATE * sizeof(u64)>>>(state_batch, params, head_w, head_b, out);
}

// round 15
// speedup vs baseline: 1.7979x; 1.7979x over previous
#include <cuda_runtime.h>
#include <cstdint>

#define NW 14
#define NSTATE (1 << NW)        // 16384 amplitudes
#define NLAYERS 6               // (DEPTH+1) * SEL_LAYERS
#define NTHREADS 512
#define NWARPS (NTHREADS / 32)
#define NPARAMS (2 * NW * 3)    // 84
#define MAXS 20

// ---------------------------------------------------------------------------
// Lazy CNOT tracking: psi[x] = a[T*x]; Rot on wire w pairs (j, j^v),
// v = col_w(T); role parity = <row_w(Tinv), j>.  swizzle sw(j)=j^(j>>4)^(j>>9).
// CNOT transitions give v_{L+1,w} = v_{L,w} ^ v_{L,w+r}: the LAST sweep of a
// layer (stride-r wire window) has a span containing ~4 next-layer gate
// vectors -> absorb them (legal: all layer-L gates already applied; absorbed
// gates run after own gates in-register).  ~13 sweeps total.
// Gates carry pair-mask mu (span-basis coefficients) and parity mask rho;
// both fold to immediates.  Lane bases keep bank-pair rank-4 (2-phase LDS).
// ---------------------------------------------------------------------------

struct LayerTab {
    uint16_t v[NW];
    uint16_t umask[NW];
    uint8_t  uidx[NW];
};
struct AllTabs {
    LayerTab lay[NLAYERS];
    uint16_t zu[NW];
};

__host__ __device__ constexpr unsigned swz(unsigned j) {
    return j ^ (j >> 4) ^ (j >> 9);
}
__host__ __device__ constexpr int popc16(uint16_t x) {
    int c = 0;
    for (int b = 0; b < 16; b++) c += (x >> b) & 1;
    return c;
}

__host__ __device__ constexpr AllTabs build_all() {
    AllTabs t{};
    uint16_t Tcol[NW]  = {};
    uint16_t TiRow[NW] = {};
    for (int i = 0; i < NW; i++) { Tcol[i] = (uint16_t)(1u << i); TiRow[i] = (uint16_t)(1u << i); }

    for (int L = 0; L < NLAYERS; L++) {
        LayerTab& lt = t.lay[L];
        for (int w = 0; w < NW; w++) {
            lt.v[w]     = Tcol[w];
            lt.umask[w] = TiRow[w];
            lt.uidx[w]  = (uint8_t)((L & 1) * NW + w);
        }
        int r = (L & 1) + 1;
        uint16_t Qrow[NW]  = {};
        uint16_t QiRow[NW] = {};
        for (int i = 0; i < NW; i++) { Qrow[i] = (uint16_t)(1u << i); QiRow[i] = (uint16_t)(1u << i); }
        for (int w = NW - 1; w >= 0; w--) Qrow[(w + r) % NW]  = (uint16_t)(Qrow[(w + r) % NW]  ^ Qrow[w]);
        for (int w = 0; w < NW; w++)      QiRow[(w + r) % NW] = (uint16_t)(QiRow[(w + r) % NW] ^ QiRow[w]);
        uint16_t nT[NW]  = {};
        uint16_t nTi[NW] = {};
        for (int w = 0; w < NW; w++) {
            uint16_t c = 0;
            for (int i = 0; i < NW; i++) if ((Qrow[i] >> w) & 1) c = (uint16_t)(c ^ Tcol[i]);
            nT[w] = c;
        }
        for (int i = 0; i < NW; i++) {
            uint16_t rr = 0;
            for (int k = 0; k < NW; k++) if ((QiRow[i] >> k) & 1) rr = (uint16_t)(rr ^ TiRow[k]);
            nTi[i] = rr;
        }
        for (int i = 0; i < NW; i++) { Tcol[i] = nT[i]; TiRow[i] = nTi[i]; }
    }
    for (int i = 0; i < NW; i++) t.zu[i] = TiRow[i];
    return t;
}

// Candidate vectors for complement-basis greedy: 14 units + 91 pairs.
__host__ __device__ constexpr uint16_t cand_vec(int idx) {
    if (idx < 14) return (uint16_t)(1u << idx);
    int k = idx - 14;
    for (int a = 0; a < 14; a++) {
        int cnt = 13 - a;
        if (k < cnt) return (uint16_t)((1u << a) | (1u << (a + 1 + k)));
        k -= cnt;
    }
    return 1;
}
#define NCAND (14 + 91)

struct GateD { uint16_t umask; uint8_t uidx; uint8_t mu; uint8_t rho; };
struct SweepD {
    int dim; int ngates;
    uint16_t spanvec[5];
    uint16_t offs[32];
    GateD g[10];
    uint16_t w[13];
};
struct Plan {
    int ns;
    SweepD s[MAXS];
};

__host__ __device__ constexpr void build_sweep_basic(const AllTabs& t, int L,
                                                     const int* wl, int take, SweepD& S) {
    S.dim = take; S.ngates = take;
    for (int i = 0; i < take; i++) {
        S.spanvec[i] = t.lay[L].v[wl[i]];
        S.g[i].umask = t.lay[L].umask[wl[i]];
        S.g[i].uidx  = t.lay[L].uidx[wl[i]];
        S.g[i].mu    = (uint8_t)(1u << i);
        S.g[i].rho   = 0;
    }
}

// Absorb next-layer gates into S (span may grow to 5 dims); marks dn[].
__host__ __device__ constexpr int absorb_into(const AllTabs& t, int Ln, SweepD& S, bool* dn) {
    uint16_t evec[14]  = {};
    uint8_t  ecoef[14] = {};
    for (int d = 0; d < S.dim; d++) {
        uint16_t x = S.spanvec[d]; uint8_t c = (uint8_t)(1u << d);
        for (int b = 13; b >= 0; b--)
            if (((x >> b) & 1) && evec[b]) { x = (uint16_t)(x ^ evec[b]); c = (uint8_t)(c ^ ecoef[b]); }
        if (x) { int b = 13; while (!((x >> b) & 1)) b--; evec[b] = x; ecoef[b] = c; }
    }
    int cnt = 0;
    for (int pass = 0; pass < 2; pass++)
        for (int w = 0; w < NW; w++) {
            if (dn[w]) continue;
            if (S.ngates >= 10) continue;
            uint16_t x = t.lay[Ln].v[w]; uint8_t c = 0;
            for (int b = 13; b >= 0; b--)
                if (((x >> b) & 1) && evec[b]) { x = (uint16_t)(x ^ evec[b]); c = (uint8_t)(c ^ ecoef[b]); }
            if (x != 0) {
                if (S.dim >= 5) continue;
                int d = S.dim;
                S.spanvec[d] = x;
                { int b = 13; while (!((x >> b) & 1)) b--; evec[b] = x; ecoef[b] = (uint8_t)(1u << d); }
                c = (uint8_t)(c ^ (1u << d));
                S.dim = d + 1;
            }
            S.g[S.ngates].umask = t.lay[Ln].umask[w];
            S.g[S.ngates].uidx  = t.lay[Ln].uidx[w];
            S.g[S.ngates].mu    = c;
            S.g[S.ngates].rho   = 0;
            S.ngates++;
            dn[w] = true;
            cnt++;
        }
    return cnt;
}

// Finalize: offsets, rho masks, lane/complement basis (bank-rank-4 first 4).
__host__ __device__ constexpr void finalize_sweep(SweepD& S) {
    for (int m = 0; m < (1 << S.dim); m++) {
        uint16_t x = 0;
        for (int d = 0; d < S.dim; d++) if ((m >> d) & 1) x = (uint16_t)(x ^ S.spanvec[d]);
        S.offs[m] = (uint16_t)swz(x);
    }
    for (int m = (1 << S.dim); m < 32; m++) S.offs[m] = 0;
    for (int gi = 0; gi < S.ngates; gi++) {
        unsigned r = 0;
        for (int d = 0; d < S.dim; d++)
            r |= (unsigned)(popc16((uint16_t)(S.g[gi].umask & S.spanvec[d])) & 1) << d;
        S.g[gi].rho = (uint8_t)r;
    }
    uint16_t ech[14] = {};
    for (int d = 0; d < S.dim; d++) {
        uint16_t x = S.spanvec[d];
        for (int b = 13; b >= 0; b--) if (((x >> b) & 1) && ech[b]) x = (uint16_t)(x ^ ech[b]);
        if (x) { int b = 13; while (!((x >> b) & 1)) b--; ech[b] = x; }
    }
    uint16_t bech[4] = {};
    const int NB = 14 - S.dim;
    for (int i = 0; i < NB; i++) {
        uint16_t pick = 0; bool found = false; bool bankok = false;
        for (int ci = 0; ci < NCAND && !found; ci++) {   // pass 1: span + bank rank
            uint16_t x0 = cand_vec(ci), x = x0;
            for (int b = 13; b >= 0; b--) if (((x >> b) & 1) && ech[b]) x = (uint16_t)(x ^ ech[b]);
            if (!x) continue;
            if (i < 4) {
                uint16_t im = (uint16_t)(swz(x0) & 15u);
                for (int b = 3; b >= 0; b--) if (((im >> b) & 1) && bech[b]) im = (uint16_t)(im ^ bech[b]);
                if (!im) continue;
            }
            pick = x0; found = true; bankok = true;
        }
        for (int ci = 0; ci < NCAND && !found; ci++) {   // pass 2: span only (fallback)
            uint16_t x0 = cand_vec(ci), x = x0;
            for (int b = 13; b >= 0; b--) if (((x >> b) & 1) && ech[b]) x = (uint16_t)(x ^ ech[b]);
            if (!x) continue;
            pick = x0; found = true; bankok = false;
        }
        {
            uint16_t x = pick;
            for (int b = 13; b >= 0; b--) if (((x >> b) & 1) && ech[b]) x = (uint16_t)(x ^ ech[b]);
            if (x) { int b = 13; while (!((x >> b) & 1)) b--; ech[b] = x; }
        }
        if (i < 4 && bankok) {
            uint16_t im = (uint16_t)(swz(pick) & 15u);
            for (int b = 3; b >= 0; b--) if (((im >> b) & 1) && bech[b]) im = (uint16_t)(im ^ bech[b]);
            if (im) { int b = 3; while (!((im >> b) & 1)) b--; bech[b] = im; }
        }
        S.w[i] = pick;
    }
    for (int i = NB; i < 13; i++) S.w[i] = 0;
}

__host__ __device__ constexpr Plan build_plan() {
    AllTabs t = build_all();
    Plan P{};
    bool done[NLAYERS][NW] = {};
    int si = 0;
    for (int L = 0; L < NLAYERS; L++) {
        int rem[NW] = {}; int nr = 0;
        for (int w2 = 0; w2 < NW; w2++) if (!done[L][w2]) rem[nr++] = w2;
        int nsw = (nr + 4) / 5;
        int lastTake = nr - 5 * (nsw - 1);
        int lastW[5] = {-1, -1, -1, -1, -1};
        if (L < NLAYERS - 1) {
            int bestCnt = -1; int bestW[5] = {-1, -1, -1, -1, -1};
            for (int s2 = 1; s2 <= 2; s2++)
                for (int a0 = 0; a0 < 14; a0++) {
                    int wl[5] = {-1, -1, -1, -1, -1}; bool ok = true;
                    for (int i = 0; i < lastTake; i++) {
                        int w2 = (a0 + s2 * i) % 14;
                        if (done[L][w2]) { ok = false; break; }
                        bool dup = false;
                        for (int j = 0; j < i; j++) if (wl[j] == w2) dup = true;
                        if (dup) { ok = false; break; }
                        wl[i] = w2;
                    }
                    if (!ok) continue;
                    SweepD Sx{}; bool dnx[NW] = {};
                    for (int q = 0; q < NW; q++) dnx[q] = done[L + 1][q];
                    build_sweep_basic(t, L, wl, lastTake, Sx);
                    int c = absorb_into(t, L + 1, Sx, dnx);
                    if (c > bestCnt) { bestCnt = c; for (int i = 0; i < 5; i++) bestW[i] = wl[i]; }
                }
            if (bestCnt >= 0) { for (int i = 0; i < 5; i++) lastW[i] = bestW[i]; }
            else { for (int i = 0; i < lastTake; i++) lastW[i] = rem[nr - lastTake + i]; }
        } else {
            for (int i = 0; i < lastTake; i++) lastW[i] = rem[nr - lastTake + i];
        }
        bool inLast[NW] = {};
        for (int i = 0; i < lastTake; i++) if (lastW[i] >= 0) inLast[lastW[i]] = true;
        int pool[NW] = {}; int np = 0;
        for (int i = 0; i < nr; i++) if (!inLast[rem[i]]) pool[np++] = rem[i];
        for (int k = 0; k < nsw - 1; k++) {
            build_sweep_basic(t, L, &pool[5 * k], 5, P.s[si]);
            finalize_sweep(P.s[si]);
            si++;
        }
        build_sweep_basic(t, L, lastW, lastTake, P.s[si]);
        if (L < NLAYERS - 1) absorb_into(t, L + 1, P.s[si], done[L + 1]);
        finalize_sweep(P.s[si]);
        si++;
        for (int w2 = 0; w2 < NW; w2++) done[L][w2] = true;
    }
    P.ns = si;
    return P;
}

// Measurement tables (zu sign masks + Walsh indices over final-sweep span),
// as a standalone constexpr function so device code can hold a LOCAL
// constexpr copy (runtime-indexable) -- namespace-scope host constexpr
// objects cannot be odr-used from device code without relaxed-constexpr.
struct MeasT { uint16_t zu[NW]; uint8_t tw[NW]; };
__host__ __device__ constexpr MeasT make_meas() {
    AllTabs t = build_all();
    Plan P = build_plan();
    const SweepD& F = P.s[P.ns - 1];
    MeasT m{};
    for (int w2 = 0; w2 < NW; w2++) {
        m.zu[w2] = t.zu[w2];
        unsigned kq = 0;
        for (int d = 0; d < F.dim; d++)
            kq |= (unsigned)(popc16((uint16_t)(F.spanvec[d] & t.zu[w2])) & 1) << d;
        m.tw[w2] = (uint8_t)kq;
    }
    return m;
}

constexpr Plan PLAN = build_plan();          // compile-time uses only
constexpr int  NS   = PLAN.ns;
static_assert(NS <= MAXS, "plan overflow");

// ---------------------------------------------------------------------------
// Packed f32x2 complex helpers. Amplitude packed as u64: lo=re, hi=im.
// ---------------------------------------------------------------------------
typedef unsigned long long u64;

__device__ __forceinline__ u64 pk(float lo, float hi) {
    u64 r; asm("mov.b64 %0, {%1,%2};" : "=l"(r) : "f"(lo), "f"(hi)); return r;
}
__device__ __forceinline__ u64 sw64(u64 a) {
    unsigned lo, hi;
    asm("mov.b64 {%0,%1}, %2;" : "=r"(lo), "=r"(hi) : "l"(a));
    u64 r; asm("mov.b64 %0, {%1,%2};" : "=l"(r) : "r"(hi), "r"(lo)); return r;
}
__device__ __forceinline__ u64 fma2_(u64 a, u64 b, u64 c) {
    u64 d; asm("fma.rn.f32x2 %0, %1, %2, %3;" : "=l"(d) : "l"(a), "l"(b), "l"(c)); return d;
}
__device__ __forceinline__ u64 mul2_(u64 a, u64 b) {
    u64 d; asm("mul.rn.f32x2 %0, %1, %2;" : "=l"(d) : "l"(a), "l"(b)); return d;
}

#define SGNC 0x8000000080000000ULL
#define ONEC 0x000000003F800000ULL   // pk(1.0f, 0.0f)

// ---------------------------------------------------------------------------
// Generic planned sweep.  INIT: registers start as the basis-state delta.
// FINAL: gates then in-register |psi|^2 measurement (Walsh), no stores.
// ---------------------------------------------------------------------------
template <int SI, bool INIT, bool FINAL>
__device__ __forceinline__ void sweepP(u64* __restrict__ st, const u64* __restrict__ Us,
                                       unsigned sj0, float* __restrict__ acc) {
    constexpr SweepD tb = build_plan().s[SI];   // local constexpr: device-safe
    constexpr int DIM = tb.dim;
    constexpr int NA = 1 << DIM;
    constexpr int NB = 14 - DIM;
    constexpr int NITER = (NSTATE >> DIM) / NTHREADS;

    unsigned rep[NITER], sj[NITER];
    u64 a[NITER][NA];
#pragma unroll
    for (int kk = 0; kk < NITER; kk++) {
        unsigned c = threadIdx.x + kk * NTHREADS;
        unsigned r = 0;
#pragma unroll
        for (int i = 0; i < NB; i++) r ^= (c & (1u << i)) ? (unsigned)tb.w[i] : 0u;
        rep[kk] = r; sj[kk] = swz(r);
        if (INIT) {
#pragma unroll
            for (int m = 0; m < NA; m++)
                a[kk][m] = ((sj[kk] ^ (unsigned)tb.offs[m]) == sj0) ? ONEC : 0ULL;
        } else {
#pragma unroll
            for (int m = 0; m < NA; m++) a[kk][m] = st[sj[kk] ^ (unsigned)tb.offs[m]];
        }
    }
#pragma unroll
    for (int gi = 0; gi < tb.ngates; gi++) {
        const u64* Ub = Us + (int)tb.g[gi].uidx * 4;     // broadcast LDS
        u64 u0 = Ub[0], u1 = Ub[1], u2 = Ub[2], u3 = Ub[3];
        const unsigned MU  = (unsigned)tb.g[gi].mu;       // immediates (gi unrolled)
        const unsigned LSB = MU & (0u - MU);
        const unsigned RHO = (unsigned)tb.g[gi].rho;
#pragma unroll
        for (int kk = 0; kk < NITER; kk++) {
            u64 bb   = (u64)(__popc(rep[kk] & (unsigned)tb.g[gi].umask) & 1u);
            u64 bmsk = (0ULL - bb) & SGNC;
            u64 A  = u0, D = u3;
            u64 B0 = u1 ^ bmsk, C0 = u2 ^ bmsk;
            u64 B1 = B0 ^ SGNC, C1 = C0 ^ SGNC;
#pragma unroll
            for (int m = 0; m < NA; m++) {
                if (m & LSB) continue;                   // one member per pair
                const int p = m ^ (int)MU;
                const bool s = (__popc((unsigned)m & RHO) & 1) != 0;   // folds
                u64 Bm = s ? B1 : B0, Cm = s ? C1 : C0;
                u64 Bx = s ? B0 : B1, Cx = s ? C0 : C1;
                u64 a0 = a[kk][m], a1 = a[kk][p];
                u64 a0s = sw64(a0), a1s = sw64(a1);
                a[kk][m] = fma2_(A, a0, fma2_(Bm, a0s, fma2_(Cm, a1, mul2_(D, a1s))));
                a[kk][p] = fma2_(A, a1, fma2_(Bx, a1s, fma2_(Cx, a0, mul2_(D, a0s))));
            }
        }
    }
    if (FINAL) {
        constexpr MeasT mt = make_meas();                // local constexpr: device-safe
#pragma unroll
        for (int kk = 0; kk < NITER; kk++) {
            float pv[NA];
#pragma unroll
            for (int m = 0; m < NA; m++) {
                float ax = __uint_as_float((unsigned)a[kk][m]);
                float ay = __uint_as_float((unsigned)(a[kk][m] >> 32));
                pv[m] = ax * ax + ay * ay;
            }
#pragma unroll
            for (int i = 0; i < DIM; i++) {
#pragma unroll
                for (int m = 0; m < NA; m++) {
                    if (m & (1 << i)) continue;
                    float x = pv[m], y = pv[m | (1 << i)];
                    pv[m] = x + y; pv[m | (1 << i)] = x - y;
                }
            }
#pragma unroll
            for (int w = 0; w < NW; w++) {
                unsigned bs = (__popc(rep[kk] & (unsigned)mt.zu[w]) & 1u) << 31;
                acc[w] += __uint_as_float(__float_as_uint(pv[mt.tw[w]]) ^ bs);
            }
        }
    } else {
#pragma unroll
        for (int kk = 0; kk < NITER; kk++)
#pragma unroll
            for (int m = 0; m < NA; m++) st[sj[kk] ^ (unsigned)tb.offs[m]] = a[kk][m];
    }
}

template <int SI>
__device__ __forceinline__ void run_all(u64* __restrict__ st, const u64* __restrict__ Us,
                                        unsigned sj0, float* __restrict__ acc) {
    if constexpr (SI < NS) {
        sweepP<SI, (SI == 0), (SI + 1 == NS)>(st, Us, sj0, acc);
        if constexpr (SI + 1 < NS) __syncthreads();
        run_all<SI + 1>(st, Us, sj0, acc);
    }
}

__global__ void __launch_bounds__(NTHREADS, 1)
qsim_kernel(const float* __restrict__ state_batch,
            const float* __restrict__ params,
            const float* __restrict__ head_w,
            const float* __restrict__ head_b,
            float* __restrict__ out) {
    extern __shared__ u64 st[];                    // 16384 x 8B = 128 KB
    __shared__ u64   Usm[2 * NW * 4];              // 28 gates x {u_rr,u_pm,v_rr,v_pm}
    __shared__ float redsm[NWARPS * NW];

    const int b   = blockIdx.x;
    const int tid = threadIdx.x;

    // 28 distinct Rot matrices (weights shared across the 3 blocks).
    // Rot = [[u, v], [-conj(v), conj(u)]]: u = e^{-i(phi+om)/2} cos(th/2),
    // v = -e^{+i(phi-om)/2} sin(th/2).
    if (tid < 2 * NW) {
        const float* p = params + (size_t)b * NPARAMS + tid * 3;
        float phi = p[0], th = p[1], om = p[2];
        float s, c;  sincosf(0.5f * th, &s, &c);
        float sa, ca; sincosf(0.5f * (phi + om), &sa, &ca);
        float sb, cb; sincosf(0.5f * (phi - om), &sb, &cb);
        float ur =  ca * c, ui = -sa * c;
        float vr = -cb * s, vi = -sb * s;
        u64* U = &Usm[tid * 4];
        U[0] = pk( ur, ur);     // u_rr
        U[1] = pk(-ui, ui);     // u_pm
        U[2] = pk( vr, vr);     // v_rr
        U[3] = pk(-vi, vi);     // v_pm
    }

    // AngleEmbedding: RX(0 or pi) -> basis state j0 (global phase irrelevant).
    unsigned j0 = 0;
    {
        const float* sb_ = state_batch + (size_t)b * (NSTATE * 2);
#pragma unroll
        for (int w = 0; w < NW; w++) if (sb_[w] < 0.f) j0 |= (1u << w);
    }
    const unsigned sj0 = swz(j0);
    __syncthreads();                                // Usm ready

    float acc[NW];
#pragma unroll
    for (int w = 0; w < NW; w++) acc[w] = 0.f;

    run_all<0>(st, Usm, sj0, acc);

    // Block-reduce acc and apply linear head
#pragma unroll
    for (int w = 0; w < NW; w++) {
#pragma unroll
        for (int o = 16; o > 0; o >>= 1) acc[w] += __shfl_xor_sync(0xffffffffu, acc[w], o);
    }
    const int lane = tid & 31, warp = tid >> 5;
    if (lane == 0) {
#pragma unroll
        for (int w = 0; w < NW; w++) redsm[warp * NW + w] = acc[w];
    }
    __syncthreads();
    if (warp == 0 && lane < NW) {
        float z = 0.f;
#pragma unroll
        for (int k = 0; k < NWARPS; k++) z += redsm[k * NW + lane];
        redsm[lane] = z * head_w[lane];
    }
    __syncthreads();
    if (tid == 0) {
        float r_ = head_b[0];
#pragma unroll
        for (int w = 0; w < NW; w++) r_ += redsm[w];
        out[b] = r_;
    }
}

extern "C" void kernel_launch(void* const* d_in, const int* in_sizes, int n_in,
                              void* d_out, int out_size) {
    const float* state_batch = (const float*)d_in[0];
    const float* params      = (const float*)d_in[1];
    const float* head_w      = (const float*)d_in[2];
    const float* head_b      = (const float*)d_in[3];
    float* out = (float*)d_out;

    int B = in_sizes[0] / (NSTATE * 2);   // 512
    cudaFuncSetAttribute(qsim_kernel, cudaFuncAttributeMaxDynamicSharedMemorySize,
                         NSTATE * (int)sizeof(u64));
    qsim_kernel<<<B, NTHREADS, NSTATE * sizeof(u64)>>>(state_batch, params, head_w, head_b, out);
}

// round 16
// speedup vs baseline: 1.8879x; 1.0501x over previous
#include <cuda_runtime.h>
#include <cstdint>

#define NW 14
#define NSTATE (1 << NW)        // 16384 amplitudes
#define NLAYERS 6               // (DEPTH+1) * SEL_LAYERS
#define NTHREADS 512
#define NWARPS (NTHREADS / 32)
#define NPARAMS (2 * NW * 3)    // 84
#define MAXS 20

// ---------------------------------------------------------------------------
// Lazy CNOT tracking: psi[x] = a[T*x]; Rot on wire w pairs (j, j^v),
// v = col_w(T); role parity = <row_w(Tinv), j>.  swizzle sw(j)=j^(j>>4)^(j>>9).
// LAYER 0 IS FREE: T=I and the embedded state is a basis state, so the state
// after layer 0 is the product  psi[x] = prod_w U_w[x_w, j0_w]  -- computed
// analytically inside the first layer-1 sweep (INIT), no sweeps for L0.
// CNOT transitions give v_{L+1,w} = v_{L,w} ^ v_{L,w+r}: the LAST sweep of a
// layer (stride-r wire window) has a span containing ~4 next-layer gate
// vectors -> absorb them.  Plan: L1: 3 sweeps, L2..L5: 2 each = 11 sweeps.
// Gates carry pair-mask mu and parity mask rho (immediates).  Lane bases
// keep bank-pair rank-4 (2-phase LDS.64/STS.64).  Measurement fused into the
// final sweep via Walsh-Hadamard.
// ---------------------------------------------------------------------------

struct LayerTab {
    uint16_t v[NW];
    uint16_t umask[NW];
    uint8_t  uidx[NW];
};
struct AllTabs {
    LayerTab lay[NLAYERS];
    uint16_t zu[NW];
};

__host__ __device__ constexpr unsigned swz(unsigned j) {
    return j ^ (j >> 4) ^ (j >> 9);
}
__host__ __device__ constexpr int popc16(uint16_t x) {
    int c = 0;
    for (int b = 0; b < 16; b++) c += (x >> b) & 1;
    return c;
}

__host__ __device__ constexpr AllTabs build_all() {
    AllTabs t{};
    uint16_t Tcol[NW]  = {};
    uint16_t TiRow[NW] = {};
    for (int i = 0; i < NW; i++) { Tcol[i] = (uint16_t)(1u << i); TiRow[i] = (uint16_t)(1u << i); }

    for (int L = 0; L < NLAYERS; L++) {
        LayerTab& lt = t.lay[L];
        for (int w = 0; w < NW; w++) {
            lt.v[w]     = Tcol[w];
            lt.umask[w] = TiRow[w];
            lt.uidx[w]  = (uint8_t)((L & 1) * NW + w);
        }
        int r = (L & 1) + 1;
        uint16_t Qrow[NW]  = {};
        uint16_t QiRow[NW] = {};
        for (int i = 0; i < NW; i++) { Qrow[i] = (uint16_t)(1u << i); QiRow[i] = (uint16_t)(1u << i); }
        for (int w = NW - 1; w >= 0; w--) Qrow[(w + r) % NW]  = (uint16_t)(Qrow[(w + r) % NW]  ^ Qrow[w]);
        for (int w = 0; w < NW; w++)      QiRow[(w + r) % NW] = (uint16_t)(QiRow[(w + r) % NW] ^ QiRow[w]);
        uint16_t nT[NW]  = {};
        uint16_t nTi[NW] = {};
        for (int w = 0; w < NW; w++) {
            uint16_t c = 0;
            for (int i = 0; i < NW; i++) if ((Qrow[i] >> w) & 1) c = (uint16_t)(c ^ Tcol[i]);
            nT[w] = c;
        }
        for (int i = 0; i < NW; i++) {
            uint16_t rr = 0;
            for (int k = 0; k < NW; k++) if ((QiRow[i] >> k) & 1) rr = (uint16_t)(rr ^ TiRow[k]);
            nTi[i] = rr;
        }
        for (int i = 0; i < NW; i++) { Tcol[i] = nT[i]; TiRow[i] = nTi[i]; }
    }
    for (int i = 0; i < NW; i++) t.zu[i] = TiRow[i];
    return t;
}

// Candidate vectors for complement-basis greedy: 14 units + 91 pairs.
__host__ __device__ constexpr uint16_t cand_vec(int idx) {
    if (idx < 14) return (uint16_t)(1u << idx);
    int k = idx - 14;
    for (int a = 0; a < 14; a++) {
        int cnt = 13 - a;
        if (k < cnt) return (uint16_t)((1u << a) | (1u << (a + 1 + k)));
        k -= cnt;
    }
    return 1;
}
#define NCAND (14 + 91)

struct GateD { uint16_t umask; uint8_t uidx; uint8_t mu; uint8_t rho; };
struct SweepD {
    int dim; int ngates;
    uint16_t spanvec[5];
    uint16_t offs[32];
    GateD g[10];
    uint16_t w[13];
};
struct Plan {
    int ns;
    SweepD s[MAXS];
};

__host__ __device__ constexpr void build_sweep_basic(const AllTabs& t, int L,
                                                     const int* wl, int take, SweepD& S) {
    S.dim = take; S.ngates = take;
    for (int i = 0; i < take; i++) {
        S.spanvec[i] = t.lay[L].v[wl[i]];
        S.g[i].umask = t.lay[L].umask[wl[i]];
        S.g[i].uidx  = t.lay[L].uidx[wl[i]];
        S.g[i].mu    = (uint8_t)(1u << i);
        S.g[i].rho   = 0;
    }
}

// Absorb next-layer gates into S (span may grow to 5 dims); marks dn[].
__host__ __device__ constexpr int absorb_into(const AllTabs& t, int Ln, SweepD& S, bool* dn) {
    uint16_t evec[14]  = {};
    uint8_t  ecoef[14] = {};
    for (int d = 0; d < S.dim; d++) {
        uint16_t x = S.spanvec[d]; uint8_t c = (uint8_t)(1u << d);
        for (int b = 13; b >= 0; b--)
            if (((x >> b) & 1) && evec[b]) { x = (uint16_t)(x ^ evec[b]); c = (uint8_t)(c ^ ecoef[b]); }
        if (x) { int b = 13; while (!((x >> b) & 1)) b--; evec[b] = x; ecoef[b] = c; }
    }
    int cnt = 0;
    for (int pass = 0; pass < 2; pass++)
        for (int w = 0; w < NW; w++) {
            if (dn[w]) continue;
            if (S.ngates >= 10) continue;
            uint16_t x = t.lay[Ln].v[w]; uint8_t c = 0;
            for (int b = 13; b >= 0; b--)
                if (((x >> b) & 1) && evec[b]) { x = (uint16_t)(x ^ evec[b]); c = (uint8_t)(c ^ ecoef[b]); }
            if (x != 0) {
                if (S.dim >= 5) continue;
                int d = S.dim;
                S.spanvec[d] = x;
                { int b = 13; while (!((x >> b) & 1)) b--; evec[b] = x; ecoef[b] = (uint8_t)(1u << d); }
                c = (uint8_t)(c ^ (1u << d));
                S.dim = d + 1;
            }
            S.g[S.ngates].umask = t.lay[Ln].umask[w];
            S.g[S.ngates].uidx  = t.lay[Ln].uidx[w];
            S.g[S.ngates].mu    = c;
            S.g[S.ngates].rho   = 0;
            S.ngates++;
            dn[w] = true;
            cnt++;
        }
    return cnt;
}

// Finalize: offsets, rho masks, lane/complement basis (bank-rank-4 first 4).
__host__ __device__ constexpr void finalize_sweep(SweepD& S) {
    for (int m = 0; m < (1 << S.dim); m++) {
        uint16_t x = 0;
        for (int d = 0; d < S.dim; d++) if ((m >> d) & 1) x = (uint16_t)(x ^ S.spanvec[d]);
        S.offs[m] = (uint16_t)swz(x);
    }
    for (int m = (1 << S.dim); m < 32; m++) S.offs[m] = 0;
    for (int gi = 0; gi < S.ngates; gi++) {
        unsigned r = 0;
        for (int d = 0; d < S.dim; d++)
            r |= (unsigned)(popc16((uint16_t)(S.g[gi].umask & S.spanvec[d])) & 1) << d;
        S.g[gi].rho = (uint8_t)r;
    }
    uint16_t ech[14] = {};
    for (int d = 0; d < S.dim; d++) {
        uint16_t x = S.spanvec[d];
        for (int b = 13; b >= 0; b--) if (((x >> b) & 1) && ech[b]) x = (uint16_t)(x ^ ech[b]);
        if (x) { int b = 13; while (!((x >> b) & 1)) b--; ech[b] = x; }
    }
    uint16_t bech[4] = {};
    const int NB = 14 - S.dim;
    for (int i = 0; i < NB; i++) {
        uint16_t pick = 0; bool found = false; bool bankok = false;
        for (int ci = 0; ci < NCAND && !found; ci++) {   // pass 1: span + bank rank
            uint16_t x0 = cand_vec(ci), x = x0;
            for (int b = 13; b >= 0; b--) if (((x >> b) & 1) && ech[b]) x = (uint16_t)(x ^ ech[b]);
            if (!x) continue;
            if (i < 4) {
                uint16_t im = (uint16_t)(swz(x0) & 15u);
                for (int b = 3; b >= 0; b--) if (((im >> b) & 1) && bech[b]) im = (uint16_t)(im ^ bech[b]);
                if (!im) continue;
            }
            pick = x0; found = true; bankok = true;
        }
        for (int ci = 0; ci < NCAND && !found; ci++) {   // pass 2: span only (fallback)
            uint16_t x0 = cand_vec(ci), x = x0;
            for (int b = 13; b >= 0; b--) if (((x >> b) & 1) && ech[b]) x = (uint16_t)(x ^ ech[b]);
            if (!x) continue;
            pick = x0; found = true; bankok = false;
        }
        {
            uint16_t x = pick;
            for (int b = 13; b >= 0; b--) if (((x >> b) & 1) && ech[b]) x = (uint16_t)(x ^ ech[b]);
            if (x) { int b = 13; while (!((x >> b) & 1)) b--; ech[b] = x; }
        }
        if (i < 4 && bankok) {
            uint16_t im = (uint16_t)(swz(pick) & 15u);
            for (int b = 3; b >= 0; b--) if (((im >> b) & 1) && bech[b]) im = (uint16_t)(im ^ bech[b]);
            if (im) { int b = 3; while (!((im >> b) & 1)) b--; bech[b] = im; }
        }
        S.w[i] = pick;
    }
    for (int i = NB; i < 13; i++) S.w[i] = 0;
}

__host__ __device__ constexpr Plan build_plan() {
    AllTabs t = build_all();
    Plan P{};
    bool done[NLAYERS][NW] = {};
    int si = 0;
    for (int L = 1; L < NLAYERS; L++) {              // layer 0 handled analytically
        int rem[NW] = {}; int nr = 0;
        for (int w2 = 0; w2 < NW; w2++) if (!done[L][w2]) rem[nr++] = w2;
        int nsw = (nr + 4) / 5;
        int lastTake = nr - 5 * (nsw - 1);
        int lastW[5] = {-1, -1, -1, -1, -1};
        if (L < NLAYERS - 1) {
            int bestCnt = -1; int bestW[5] = {-1, -1, -1, -1, -1};
            for (int s2 = 1; s2 <= 2; s2++)
                for (int a0 = 0; a0 < 14; a0++) {
                    int wl[5] = {-1, -1, -1, -1, -1}; bool ok = true;
                    for (int i = 0; i < lastTake; i++) {
                        int w2 = (a0 + s2 * i) % 14;
                        if (done[L][w2]) { ok = false; break; }
                        bool dup = false;
                        for (int j = 0; j < i; j++) if (wl[j] == w2) dup = true;
                        if (dup) { ok = false; break; }
                        wl[i] = w2;
                    }
                    if (!ok) continue;
                    SweepD Sx{}; bool dnx[NW] = {};
                    for (int q = 0; q < NW; q++) dnx[q] = done[L + 1][q];
                    build_sweep_basic(t, L, wl, lastTake, Sx);
                    int c = absorb_into(t, L + 1, Sx, dnx);
                    if (c > bestCnt) { bestCnt = c; for (int i = 0; i < 5; i++) bestW[i] = wl[i]; }
                }
            if (bestCnt >= 0) { for (int i = 0; i < 5; i++) lastW[i] = bestW[i]; }
            else { for (int i = 0; i < lastTake; i++) lastW[i] = rem[nr - lastTake + i]; }
        } else {
            for (int i = 0; i < lastTake; i++) lastW[i] = rem[nr - lastTake + i];
        }
        bool inLast[NW] = {};
        for (int i = 0; i < lastTake; i++) if (lastW[i] >= 0) inLast[lastW[i]] = true;
        int pool[NW] = {}; int np = 0;
        for (int i = 0; i < nr; i++) if (!inLast[rem[i]]) pool[np++] = rem[i];
        for (int k = 0; k < nsw - 1; k++) {
            build_sweep_basic(t, L, &pool[5 * k], 5, P.s[si]);
            finalize_sweep(P.s[si]);
            si++;
        }
        build_sweep_basic(t, L, lastW, lastTake, P.s[si]);
        if (L < NLAYERS - 1) absorb_into(t, L + 1, P.s[si], done[L + 1]);
        finalize_sweep(P.s[si]);
        si++;
        for (int w2 = 0; w2 < NW; w2++) done[L][w2] = true;
    }
    P.ns = si;
    return P;
}

// Measurement tables (local-constexpr instantiable in device code).
struct MeasT { uint16_t zu[NW]; uint8_t tw[NW]; };
__host__ __device__ constexpr MeasT make_meas() {
    AllTabs t = build_all();
    Plan P = build_plan();
    const SweepD& F = P.s[P.ns - 1];
    MeasT m{};
    for (int w2 = 0; w2 < NW; w2++) {
        m.zu[w2] = t.zu[w2];
        unsigned kq = 0;
        for (int d = 0; d < F.dim; d++)
            kq |= (unsigned)(popc16((uint16_t)(F.spanvec[d] & t.zu[w2])) & 1) << d;
        m.tw[w2] = (uint8_t)kq;
    }
    return m;
}

// INIT product tables: kmask[w] = which span dims of sweep 0 touch wire w.
struct InitT { uint8_t kmask[NW]; };
__host__ __device__ constexpr InitT make_init() {
    Plan P = build_plan();
    const SweepD& S = P.s[0];
    InitT it{};
    for (int w = 0; w < NW; w++) {
        unsigned k = 0;
        for (int d = 0; d < S.dim; d++) k |= (unsigned)((S.spanvec[d] >> w) & 1u) << d;
        it.kmask[w] = (uint8_t)k;
    }
    return it;
}

constexpr Plan PLAN = build_plan();          // compile-time uses only
constexpr int  NS   = PLAN.ns;
static_assert(NS <= MAXS, "plan overflow");

// ---------------------------------------------------------------------------
// Packed f32x2 complex helpers. Amplitude packed as u64: lo=re, hi=im.
// ---------------------------------------------------------------------------
typedef unsigned long long u64;

__device__ __forceinline__ u64 pk(float lo, float hi) {
    u64 r; asm("mov.b64 %0, {%1,%2};" : "=l"(r) : "f"(lo), "f"(hi)); return r;
}
__device__ __forceinline__ u64 sw64(u64 a) {
    unsigned lo, hi;
    asm("mov.b64 {%0,%1}, %2;" : "=r"(lo), "=r"(hi) : "l"(a));
    u64 r; asm("mov.b64 %0, {%1,%2};" : "=l"(r) : "r"(hi), "r"(lo)); return r;
}
__device__ __forceinline__ u64 fma2_(u64 a, u64 b, u64 c) {
    u64 d; asm("fma.rn.f32x2 %0, %1, %2, %3;" : "=l"(d) : "l"(a), "l"(b), "l"(c)); return d;
}
__device__ __forceinline__ u64 mul2_(u64 a, u64 b) {
    u64 d; asm("mul.rn.f32x2 %0, %1, %2;" : "=l"(d) : "l"(a), "l"(b)); return d;
}
// multiply amplitude P by complex g given as (g_rr, g_pm)
__device__ __forceinline__ u64 cmulg(u64 grr, u64 gpm, u64 P) {
    return fma2_(grr, P, mul2_(gpm, sw64(P)));
}

#define SGNC 0x8000000080000000ULL
#define ONEC 0x000000003F800000ULL   // pk(1.0f, 0.0f)

// ---------------------------------------------------------------------------
// Generic planned sweep.  INIT: registers start as the layer-0 product state
// (no SMEM load).  FINAL: gates then in-register measurement (Walsh).
// ---------------------------------------------------------------------------
template <int SI, bool INIT, bool FINAL>
__device__ __forceinline__ void sweepP(u64* __restrict__ st, const u64* __restrict__ Us,
                                       const u64* __restrict__ Gs, float* __restrict__ acc) {
    constexpr SweepD tb = build_plan().s[SI];   // local constexpr: device-safe
    constexpr int DIM = tb.dim;
    constexpr int NA = 1 << DIM;
    constexpr int NB = 14 - DIM;
    constexpr int NITER = (NSTATE >> DIM) / NTHREADS;

    unsigned rep[NITER], sj[NITER];
    u64 a[NITER][NA];
#pragma unroll
    for (int kk = 0; kk < NITER; kk++) {
        unsigned c = threadIdx.x + kk * NTHREADS;
        unsigned r = 0;
#pragma unroll
        for (int i = 0; i < NB; i++) r ^= (c & (1u << i)) ? (unsigned)tb.w[i] : 0u;
        rep[kk] = r; sj[kk] = swz(r);
        if (!INIT) {
#pragma unroll
            for (int m = 0; m < NA; m++) a[kk][m] = st[sj[kk] ^ (unsigned)tb.offs[m]];
        }
    }
    if (INIT) {
        // Layer-0 product state: a[m] = prod_w g_w(x_w), x = rep ^ span-offset.
        constexpr InitT it = make_init();
        u64 C = ONEC;
#pragma unroll
        for (int w = 0; w < NW; w++) {
            if (it.kmask[w] == 0) {                      // constant over the coset
                const u64* Gw = Gs + w * 4;
                bool b1 = (rep[0] >> w) & 1u;
                C = cmulg(b1 ? Gw[2] : Gw[0], b1 ? Gw[3] : Gw[1], C);
            }
        }
#pragma unroll
        for (int m = 0; m < NA; m++) a[0][m] = C;
#pragma unroll
        for (int w = 0; w < NW; w++) {
            if (it.kmask[w] != 0) {
                const u64* Gw = Gs + w * 4;
                bool b1 = (rep[0] >> w) & 1u;
                u64 gArr = b1 ? Gw[2] : Gw[0], gApm = b1 ? Gw[3] : Gw[1];
                u64 gBrr = b1 ? Gw[0] : Gw[2], gBpm = b1 ? Gw[1] : Gw[3];
#pragma unroll
                for (int m = 0; m < NA; m++) {
                    const bool pm_ = (__popc((unsigned)m & (unsigned)it.kmask[w]) & 1) != 0;  // folds
                    a[0][m] = cmulg(pm_ ? gBrr : gArr, pm_ ? gBpm : gApm, a[0][m]);
                }
            }
        }
    }
#pragma unroll
    for (int gi = 0; gi < tb.ngates; gi++) {
        const u64* Ub = Us + (int)tb.g[gi].uidx * 4;     // broadcast LDS
        u64 u0 = Ub[0], u1 = Ub[1], u2 = Ub[2], u3 = Ub[3];
        const unsigned MU  = (unsigned)tb.g[gi].mu;       // immediates (gi unrolled)
        const unsigned LSB = MU & (0u - MU);
        const unsigned RHO = (unsigned)tb.g[gi].rho;
#pragma unroll
        for (int kk = 0; kk < NITER; kk++) {
            u64 bb   = (u64)(__popc(rep[kk] & (unsigned)tb.g[gi].umask) & 1u);
            u64 bmsk = (0ULL - bb) & SGNC;
            u64 A  = u0, D = u3;
            u64 B0 = u1 ^ bmsk, C0 = u2 ^ bmsk;
            u64 B1 = B0 ^ SGNC, C1 = C0 ^ SGNC;
#pragma unroll
            for (int m = 0; m < NA; m++) {
                if (m & LSB) continue;                   // one member per pair
                const int p = m ^ (int)MU;
                const bool s = (__popc((unsigned)m & RHO) & 1) != 0;   // folds
                u64 Bm = s ? B1 : B0, Cm = s ? C1 : C0;
                u64 Bx = s ? B0 : B1, Cx = s ? C0 : C1;
                u64 a0 = a[kk][m], a1 = a[kk][p];
                u64 a0s = sw64(a0), a1s = sw64(a1);
                a[kk][m] = fma2_(A, a0, fma2_(Bm, a0s, fma2_(Cm, a1, mul2_(D, a1s))));
                a[kk][p] = fma2_(A, a1, fma2_(Bx, a1s, fma2_(Cx, a0, mul2_(D, a0s))));
            }
        }
    }
    if (FINAL) {
        constexpr MeasT mt = make_meas();                // local constexpr: device-safe
#pragma unroll
        for (int kk = 0; kk < NITER; kk++) {
            float pv[NA];
#pragma unroll
            for (int m = 0; m < NA; m++) {
                float ax = __uint_as_float((unsigned)a[kk][m]);
                float ay = __uint_as_float((unsigned)(a[kk][m] >> 32));
                pv[m] = ax * ax + ay * ay;
            }
#pragma unroll
            for (int i = 0; i < DIM; i++) {
#pragma unroll
                for (int m = 0; m < NA; m++) {
                    if (m & (1 << i)) continue;
                    float x = pv[m], y = pv[m | (1 << i)];
                    pv[m] = x + y; pv[m | (1 << i)] = x - y;
                }
            }
#pragma unroll
            for (int w = 0; w < NW; w++) {
                unsigned bs = (__popc(rep[kk] & (unsigned)mt.zu[w]) & 1u) << 31;
                acc[w] += __uint_as_float(__float_as_uint(pv[mt.tw[w]]) ^ bs);
            }
        }
    } else {
#pragma unroll
        for (int kk = 0; kk < NITER; kk++)
#pragma unroll
            for (int m = 0; m < NA; m++) st[sj[kk] ^ (unsigned)tb.offs[m]] = a[kk][m];
    }
}

template <int SI>
__device__ __forceinline__ void run_all(u64* __restrict__ st, const u64* __restrict__ Us,
                                        const u64* __restrict__ Gs, float* __restrict__ acc) {
    if constexpr (SI < NS) {
        sweepP<SI, (SI == 0), (SI + 1 == NS)>(st, Us, Gs, acc);
        if constexpr (SI + 1 < NS) __syncthreads();
        run_all<SI + 1>(st, Us, Gs, acc);
    }
}

__global__ void __launch_bounds__(NTHREADS, 1)
qsim_kernel(const float* __restrict__ state_batch,
            const float* __restrict__ params,
            const float* __restrict__ head_w,
            const float* __restrict__ head_b,
            float* __restrict__ out) {
    extern __shared__ u64 st[];                    // 16384 x 8B = 128 KB
    __shared__ u64   Usm[2 * NW * 4];              // 28 gates x {u_rr,u_pm,v_rr,v_pm}
    __shared__ u64   Gsm[NW * 4];                  // layer-0 column factors g0,g1 (rr,pm)
    __shared__ float redsm[NWARPS * NW];

    const int b   = blockIdx.x;
    const int tid = threadIdx.x;

    // 28 distinct Rot matrices (weights shared across the 3 blocks).
    // Rot = [[u, v], [-conj(v), conj(u)]]: u = e^{-i(phi+om)/2} cos(th/2),
    // v = -e^{+i(phi-om)/2} sin(th/2).
    if (tid < 2 * NW) {
        const float* p = params + (size_t)b * NPARAMS + tid * 3;
        float phi = p[0], th = p[1], om = p[2];
        float s, c;  sincosf(0.5f * th, &s, &c);
        float sa, ca; sincosf(0.5f * (phi + om), &sa, &ca);
        float sb, cb; sincosf(0.5f * (phi - om), &sb, &cb);
        float ur =  ca * c, ui = -sa * c;
        float vr = -cb * s, vi = -sb * s;
        u64* U = &Usm[tid * 4];
        U[0] = pk( ur, ur);     // u_rr
        U[1] = pk(-ui, ui);     // u_pm
        U[2] = pk( vr, vr);     // v_rr
        U[3] = pk(-vi, vi);     // v_pm
        // Layer-0 column factors for the analytic product state (wires tid<NW,
        // l=0 weights = same param rows).  Column j0_w of U:
        //   j0=0: g0=u00=u,  g1=u10=-conj(v);  j0=1: g0=u01=v, g1=u11=conj(u).
        if (tid < NW) {
            bool j0b = state_batch[(size_t)b * (NSTATE * 2) + tid] < 0.f;
            float g0r, g0i, g1r, g1i;
            if (!j0b) { g0r = ur; g0i = ui; g1r = -vr; g1i = vi; }
            else      { g0r = vr; g0i = vi; g1r = ur;  g1i = -ui; }
            u64* G = &Gsm[tid * 4];
            G[0] = pk( g0r, g0r);
            G[1] = pk(-g0i, g0i);
            G[2] = pk( g1r, g1r);
            G[3] = pk(-g1i, g1i);
        }
    }
    __syncthreads();                                // Usm, Gsm ready

    float acc[NW];
#pragma unroll
    for (int w = 0; w < NW; w++) acc[w] = 0.f;

    run_all<0>(st, Usm, Gsm, acc);

    // Block-reduce acc and apply linear head
#pragma unroll
    for (int w = 0; w < NW; w++) {
#pragma unroll
        for (int o = 16; o > 0; o >>= 1) acc[w] += __shfl_xor_sync(0xffffffffu, acc[w], o);
    }
    const int lane = tid & 31, warp = tid >> 5;
    if (lane == 0) {
#pragma unroll
        for (int w = 0; w < NW; w++) redsm[warp * NW + w] = acc[w];
    }
    __syncthreads();
    if (warp == 0 && lane < NW) {
        float z = 0.f;
#pragma unroll
        for (int k = 0; k < NWARPS; k++) z += redsm[k * NW + lane];
        redsm[lane] = z * head_w[lane];
    }
    __syncthreads();
    if (tid == 0) {
        float r_ = head_b[0];
#pragma unroll
        for (int w = 0; w < NW; w++) r_ += redsm[w];
        out[b] = r_;
    }
}

extern "C" void kernel_launch(void* const* d_in, const int* in_sizes, int n_in,
                              void* d_out, int out_size) {
    const float* state_batch = (const float*)d_in[0];
    const float* params      = (const float*)d_in[1];
    const float* head_w      = (const float*)d_in[2];
    const float* head_b      = (const float*)d_in[3];
    float* out = (float*)d_out;

    int B = in_sizes[0] / (NSTATE * 2);   // 512
    cudaFuncSetAttribute(qsim_kernel, cudaFuncAttributeMaxDynamicSharedMemorySize,
                         NSTATE * (int)sizeof(u64));
    qsim_kernel<<<B, NTHREADS, NSTATE * sizeof(u64)>>>(state_batch, params, head_w, head_b, out);
}

// round 17
// speedup vs baseline: 1.9047x; 1.0089x over previous
#include <cuda_runtime.h>
#include <cstdint>

#define NW 14
#define NSTATE (1 << NW)        // 16384 amplitudes
#define NLAYERS 6               // (DEPTH+1) * SEL_LAYERS
#define NTHREADS 512
#define NWARPS (NTHREADS / 32)
#define NPARAMS (2 * NW * 3)    // 84
#define MAXS 20

// ---------------------------------------------------------------------------
// Lazy CNOT tracking: psi[x] = a[T*x]; Rot on wire w pairs (j, j^v),
// v = col_w(T); role parity = <row_w(Tinv), j>.  swizzle sw(j)=j^(j>>4)^(j>>9).
// LAYER 0 IS FREE: analytic product state folded into the first sweep (INIT).
// Cross-layer absorption: last sweep of each layer absorbs ~4 next-layer
// gates (span containment via v_{L+1,w} = v_{L,w} ^ v_{L,w+r}).  11 sweeps.
// Measurement: FINAL sweep accumulates <Z_w> directly with compile-time
// per-(m,w) signs (no pv[] Walsh array -> no register spill).
// ---------------------------------------------------------------------------

struct LayerTab {
    uint16_t v[NW];
    uint16_t umask[NW];
    uint8_t  uidx[NW];
};
struct AllTabs {
    LayerTab lay[NLAYERS];
    uint16_t zu[NW];
};

__host__ __device__ constexpr unsigned swz(unsigned j) {
    return j ^ (j >> 4) ^ (j >> 9);
}
__host__ __device__ constexpr int popc16(uint16_t x) {
    int c = 0;
    for (int b = 0; b < 16; b++) c += (x >> b) & 1;
    return c;
}

__host__ __device__ constexpr AllTabs build_all() {
    AllTabs t{};
    uint16_t Tcol[NW]  = {};
    uint16_t TiRow[NW] = {};
    for (int i = 0; i < NW; i++) { Tcol[i] = (uint16_t)(1u << i); TiRow[i] = (uint16_t)(1u << i); }

    for (int L = 0; L < NLAYERS; L++) {
        LayerTab& lt = t.lay[L];
        for (int w = 0; w < NW; w++) {
            lt.v[w]     = Tcol[w];
            lt.umask[w] = TiRow[w];
            lt.uidx[w]  = (uint8_t)((L & 1) * NW + w);
        }
        int r = (L & 1) + 1;
        uint16_t Qrow[NW]  = {};
        uint16_t QiRow[NW] = {};
        for (int i = 0; i < NW; i++) { Qrow[i] = (uint16_t)(1u << i); QiRow[i] = (uint16_t)(1u << i); }
        for (int w = NW - 1; w >= 0; w--) Qrow[(w + r) % NW]  = (uint16_t)(Qrow[(w + r) % NW]  ^ Qrow[w]);
        for (int w = 0; w < NW; w++)      QiRow[(w + r) % NW] = (uint16_t)(QiRow[(w + r) % NW] ^ QiRow[w]);
        uint16_t nT[NW]  = {};
        uint16_t nTi[NW] = {};
        for (int w = 0; w < NW; w++) {
            uint16_t c = 0;
            for (int i = 0; i < NW; i++) if ((Qrow[i] >> w) & 1) c = (uint16_t)(c ^ Tcol[i]);
            nT[w] = c;
        }
        for (int i = 0; i < NW; i++) {
            uint16_t rr = 0;
            for (int k = 0; k < NW; k++) if ((QiRow[i] >> k) & 1) rr = (uint16_t)(rr ^ TiRow[k]);
            nTi[i] = rr;
        }
        for (int i = 0; i < NW; i++) { Tcol[i] = nT[i]; TiRow[i] = nTi[i]; }
    }
    for (int i = 0; i < NW; i++) t.zu[i] = TiRow[i];
    return t;
}

// Candidate vectors for complement-basis greedy: 14 units + 91 pairs.
__host__ __device__ constexpr uint16_t cand_vec(int idx) {
    if (idx < 14) return (uint16_t)(1u << idx);
    int k = idx - 14;
    for (int a = 0; a < 14; a++) {
        int cnt = 13 - a;
        if (k < cnt) return (uint16_t)((1u << a) | (1u << (a + 1 + k)));
        k -= cnt;
    }
    return 1;
}
#define NCAND (14 + 91)

struct GateD { uint16_t umask; uint8_t uidx; uint8_t mu; uint8_t rho; };
struct SweepD {
    int dim; int ngates;
    uint16_t spanvec[5];
    uint16_t offs[32];
    GateD g[10];
    uint16_t w[13];
};
struct Plan {
    int ns;
    SweepD s[MAXS];
};

__host__ __device__ constexpr void build_sweep_basic(const AllTabs& t, int L,
                                                     const int* wl, int take, SweepD& S) {
    S.dim = take; S.ngates = take;
    for (int i = 0; i < take; i++) {
        S.spanvec[i] = t.lay[L].v[wl[i]];
        S.g[i].umask = t.lay[L].umask[wl[i]];
        S.g[i].uidx  = t.lay[L].uidx[wl[i]];
        S.g[i].mu    = (uint8_t)(1u << i);
        S.g[i].rho   = 0;
    }
}

// Absorb next-layer gates into S (span may grow to 5 dims); marks dn[].
__host__ __device__ constexpr int absorb_into(const AllTabs& t, int Ln, SweepD& S, bool* dn) {
    uint16_t evec[14]  = {};
    uint8_t  ecoef[14] = {};
    for (int d = 0; d < S.dim; d++) {
        uint16_t x = S.spanvec[d]; uint8_t c = (uint8_t)(1u << d);
        for (int b = 13; b >= 0; b--)
            if (((x >> b) & 1) && evec[b]) { x = (uint16_t)(x ^ evec[b]); c = (uint8_t)(c ^ ecoef[b]); }
        if (x) { int b = 13; while (!((x >> b) & 1)) b--; evec[b] = x; ecoef[b] = c; }
    }
    int cnt = 0;
    for (int pass = 0; pass < 2; pass++)
        for (int w = 0; w < NW; w++) {
            if (dn[w]) continue;
            if (S.ngates >= 10) continue;
            uint16_t x = t.lay[Ln].v[w]; uint8_t c = 0;
            for (int b = 13; b >= 0; b--)
                if (((x >> b) & 1) && evec[b]) { x = (uint16_t)(x ^ evec[b]); c = (uint8_t)(c ^ ecoef[b]); }
            if (x != 0) {
                if (S.dim >= 5) continue;
                int d = S.dim;
                S.spanvec[d] = x;
                { int b = 13; while (!((x >> b) & 1)) b--; evec[b] = x; ecoef[b] = (uint8_t)(1u << d); }
                c = (uint8_t)(c ^ (1u << d));
                S.dim = d + 1;
            }
            S.g[S.ngates].umask = t.lay[Ln].umask[w];
            S.g[S.ngates].uidx  = t.lay[Ln].uidx[w];
            S.g[S.ngates].mu    = c;
            S.g[S.ngates].rho   = 0;
            S.ngates++;
            dn[w] = true;
            cnt++;
        }
    return cnt;
}

// Finalize: offsets, rho masks, lane/complement basis (bank-rank-4 first 4).
__host__ __device__ constexpr void finalize_sweep(SweepD& S) {
    for (int m = 0; m < (1 << S.dim); m++) {
        uint16_t x = 0;
        for (int d = 0; d < S.dim; d++) if ((m >> d) & 1) x = (uint16_t)(x ^ S.spanvec[d]);
        S.offs[m] = (uint16_t)swz(x);
    }
    for (int m = (1 << S.dim); m < 32; m++) S.offs[m] = 0;
    for (int gi = 0; gi < S.ngates; gi++) {
        unsigned r = 0;
        for (int d = 0; d < S.dim; d++)
            r |= (unsigned)(popc16((uint16_t)(S.g[gi].umask & S.spanvec[d])) & 1) << d;
        S.g[gi].rho = (uint8_t)r;
    }
    uint16_t ech[14] = {};
    for (int d = 0; d < S.dim; d++) {
        uint16_t x = S.spanvec[d];
        for (int b = 13; b >= 0; b--) if (((x >> b) & 1) && ech[b]) x = (uint16_t)(x ^ ech[b]);
        if (x) { int b = 13; while (!((x >> b) & 1)) b--; ech[b] = x; }
    }
    uint16_t bech[4] = {};
    const int NB = 14 - S.dim;
    for (int i = 0; i < NB; i++) {
        uint16_t pick = 0; bool found = false; bool bankok = false;
        for (int ci = 0; ci < NCAND && !found; ci++) {   // pass 1: span + bank rank
            uint16_t x0 = cand_vec(ci), x = x0;
            for (int b = 13; b >= 0; b--) if (((x >> b) & 1) && ech[b]) x = (uint16_t)(x ^ ech[b]);
            if (!x) continue;
            if (i < 4) {
                uint16_t im = (uint16_t)(swz(x0) & 15u);
                for (int b = 3; b >= 0; b--) if (((im >> b) & 1) && bech[b]) im = (uint16_t)(im ^ bech[b]);
                if (!im) continue;
            }
            pick = x0; found = true; bankok = true;
        }
        for (int ci = 0; ci < NCAND && !found; ci++) {   // pass 2: span only (fallback)
            uint16_t x0 = cand_vec(ci), x = x0;
            for (int b = 13; b >= 0; b--) if (((x >> b) & 1) && ech[b]) x = (uint16_t)(x ^ ech[b]);
            if (!x) continue;
            pick = x0; found = true; bankok = false;
        }
        {
            uint16_t x = pick;
            for (int b = 13; b >= 0; b--) if (((x >> b) & 1) && ech[b]) x = (uint16_t)(x ^ ech[b]);
            if (x) { int b = 13; while (!((x >> b) & 1)) b--; ech[b] = x; }
        }
        if (i < 4 && bankok) {
            uint16_t im = (uint16_t)(swz(pick) & 15u);
            for (int b = 3; b >= 0; b--) if (((im >> b) & 1) && bech[b]) im = (uint16_t)(im ^ bech[b]);
            if (im) { int b = 3; while (!((im >> b) & 1)) b--; bech[b] = im; }
        }
        S.w[i] = pick;
    }
    for (int i = NB; i < 13; i++) S.w[i] = 0;
}

__host__ __device__ constexpr Plan build_plan() {
    AllTabs t = build_all();
    Plan P{};
    bool done[NLAYERS][NW] = {};
    int si = 0;
    for (int L = 1; L < NLAYERS; L++) {              // layer 0 handled analytically
        int rem[NW] = {}; int nr = 0;
        for (int w2 = 0; w2 < NW; w2++) if (!done[L][w2]) rem[nr++] = w2;
        int nsw = (nr + 4) / 5;
        int lastTake = nr - 5 * (nsw - 1);
        int lastW[5] = {-1, -1, -1, -1, -1};
        if (L < NLAYERS - 1) {
            int bestCnt = -1; int bestW[5] = {-1, -1, -1, -1, -1};
            for (int s2 = 1; s2 <= 2; s2++)
                for (int a0 = 0; a0 < 14; a0++) {
                    int wl[5] = {-1, -1, -1, -1, -1}; bool ok = true;
                    for (int i = 0; i < lastTake; i++) {
                        int w2 = (a0 + s2 * i) % 14;
                        if (done[L][w2]) { ok = false; break; }
                        bool dup = false;
                        for (int j = 0; j < i; j++) if (wl[j] == w2) dup = true;
                        if (dup) { ok = false; break; }
                        wl[i] = w2;
                    }
                    if (!ok) continue;
                    SweepD Sx{}; bool dnx[NW] = {};
                    for (int q = 0; q < NW; q++) dnx[q] = done[L + 1][q];
                    build_sweep_basic(t, L, wl, lastTake, Sx);
                    int c = absorb_into(t, L + 1, Sx, dnx);
                    if (c > bestCnt) { bestCnt = c; for (int i = 0; i < 5; i++) bestW[i] = wl[i]; }
                }
            if (bestCnt >= 0) { for (int i = 0; i < 5; i++) lastW[i] = bestW[i]; }
            else { for (int i = 0; i < lastTake; i++) lastW[i] = rem[nr - lastTake + i]; }
        } else {
            for (int i = 0; i < lastTake; i++) lastW[i] = rem[nr - lastTake + i];
        }
        bool inLast[NW] = {};
        for (int i = 0; i < lastTake; i++) if (lastW[i] >= 0) inLast[lastW[i]] = true;
        int pool[NW] = {}; int np = 0;
        for (int i = 0; i < nr; i++) if (!inLast[rem[i]]) pool[np++] = rem[i];
        for (int k = 0; k < nsw - 1; k++) {
            build_sweep_basic(t, L, &pool[5 * k], 5, P.s[si]);
            finalize_sweep(P.s[si]);
            si++;
        }
        build_sweep_basic(t, L, lastW, lastTake, P.s[si]);
        if (L < NLAYERS - 1) absorb_into(t, L + 1, P.s[si], done[L + 1]);
        finalize_sweep(P.s[si]);
        si++;
        for (int w2 = 0; w2 < NW; w2++) done[L][w2] = true;
    }
    P.ns = si;
    return P;
}

// Measurement tables (local-constexpr instantiable in device code).
struct MeasT { uint16_t zu[NW]; uint8_t tw[NW]; };
__host__ __device__ constexpr MeasT make_meas() {
    AllTabs t = build_all();
    Plan P = build_plan();
    const SweepD& F = P.s[P.ns - 1];
    MeasT m{};
    for (int w2 = 0; w2 < NW; w2++) {
        m.zu[w2] = t.zu[w2];
        unsigned kq = 0;
        for (int d = 0; d < F.dim; d++)
            kq |= (unsigned)(popc16((uint16_t)(F.spanvec[d] & t.zu[w2])) & 1) << d;
        m.tw[w2] = (uint8_t)kq;
    }
    return m;
}

// INIT product tables: kmask[w] = which span dims of sweep 0 touch wire w.
struct InitT { uint8_t kmask[NW]; };
__host__ __device__ constexpr InitT make_init() {
    Plan P = build_plan();
    const SweepD& S = P.s[0];
    InitT it{};
    for (int w = 0; w < NW; w++) {
        unsigned k = 0;
        for (int d = 0; d < S.dim; d++) k |= (unsigned)((S.spanvec[d] >> w) & 1u) << d;
        it.kmask[w] = (uint8_t)k;
    }
    return it;
}

constexpr Plan PLAN = build_plan();          // compile-time uses only
constexpr int  NS   = PLAN.ns;
static_assert(NS <= MAXS, "plan overflow");

// ---------------------------------------------------------------------------
// Packed f32x2 complex helpers. Amplitude packed as u64: lo=re, hi=im.
// ---------------------------------------------------------------------------
typedef unsigned long long u64;

__device__ __forceinline__ u64 pk(float lo, float hi) {
    u64 r; asm("mov.b64 %0, {%1,%2};" : "=l"(r) : "f"(lo), "f"(hi)); return r;
}
__device__ __forceinline__ u64 sw64(u64 a) {
    unsigned lo, hi;
    asm("mov.b64 {%0,%1}, %2;" : "=r"(lo), "=r"(hi) : "l"(a));
    u64 r; asm("mov.b64 %0, {%1,%2};" : "=l"(r) : "r"(hi), "r"(lo)); return r;
}
__device__ __forceinline__ u64 fma2_(u64 a, u64 b, u64 c) {
    u64 d; asm("fma.rn.f32x2 %0, %1, %2, %3;" : "=l"(d) : "l"(a), "l"(b), "l"(c)); return d;
}
__device__ __forceinline__ u64 mul2_(u64 a, u64 b) {
    u64 d; asm("mul.rn.f32x2 %0, %1, %2;" : "=l"(d) : "l"(a), "l"(b)); return d;
}
// multiply amplitude P by complex g given as (g_rr, g_pm)
__device__ __forceinline__ u64 cmulg(u64 grr, u64 gpm, u64 P) {
    return fma2_(grr, P, mul2_(gpm, sw64(P)));
}

#define SGNC 0x8000000080000000ULL
#define ONEC 0x000000003F800000ULL   // pk(1.0f, 0.0f)

// ---------------------------------------------------------------------------
// Generic planned sweep.  INIT: registers start as the layer-0 product state
// (no SMEM load).  FINAL: gates then direct signed <Z_w> accumulation with
// compile-time per-(m,w) signs (no pv[] array -> no spill).
// ---------------------------------------------------------------------------
template <int SI, bool INIT, bool FINAL>
__device__ __forceinline__ void sweepP(u64* __restrict__ st, const u64* __restrict__ Us,
                                       const u64* __restrict__ Gs, float* __restrict__ acc) {
    constexpr SweepD tb = build_plan().s[SI];   // local constexpr: device-safe
    constexpr int DIM = tb.dim;
    constexpr int NA = 1 << DIM;
    constexpr int NB = 14 - DIM;
    constexpr int NITER = (NSTATE >> DIM) / NTHREADS;

    unsigned rep[NITER], sj[NITER];
    u64 a[NITER][NA];
#pragma unroll
    for (int kk = 0; kk < NITER; kk++) {
        unsigned c = threadIdx.x + kk * NTHREADS;
        unsigned r = 0;
#pragma unroll
        for (int i = 0; i < NB; i++) r ^= (c & (1u << i)) ? (unsigned)tb.w[i] : 0u;
        rep[kk] = r; sj[kk] = swz(r);
        if (!INIT) {
#pragma unroll
            for (int m = 0; m < NA; m++) a[kk][m] = st[sj[kk] ^ (unsigned)tb.offs[m]];
        }
    }
    if (INIT) {
        // Layer-0 product state: a[m] = prod_w g_w(x_w), x = rep ^ span-offset.
        constexpr InitT it = make_init();
        u64 C = ONEC;
#pragma unroll
        for (int w = 0; w < NW; w++) {
            if (it.kmask[w] == 0) {                      // constant over the coset
                const u64* Gw = Gs + w * 4;
                bool b1 = (rep[0] >> w) & 1u;
                C = cmulg(b1 ? Gw[2] : Gw[0], b1 ? Gw[3] : Gw[1], C);
            }
        }
#pragma unroll
        for (int m = 0; m < NA; m++) a[0][m] = C;
#pragma unroll
        for (int w = 0; w < NW; w++) {
            if (it.kmask[w] != 0) {
                const u64* Gw = Gs + w * 4;
                bool b1 = (rep[0] >> w) & 1u;
                u64 gArr = b1 ? Gw[2] : Gw[0], gApm = b1 ? Gw[3] : Gw[1];
                u64 gBrr = b1 ? Gw[0] : Gw[2], gBpm = b1 ? Gw[1] : Gw[3];
#pragma unroll
                for (int m = 0; m < NA; m++) {
                    const bool pm_ = (__popc((unsigned)m & (unsigned)it.kmask[w]) & 1) != 0;  // folds
                    a[0][m] = cmulg(pm_ ? gBrr : gArr, pm_ ? gBpm : gApm, a[0][m]);
                }
            }
        }
    }
#pragma unroll
    for (int gi = 0; gi < tb.ngates; gi++) {
        const u64* Ub = Us + (int)tb.g[gi].uidx * 4;     // broadcast LDS
        u64 u0 = Ub[0], u1 = Ub[1], u2 = Ub[2], u3 = Ub[3];
        const unsigned MU  = (unsigned)tb.g[gi].mu;       // immediates (gi unrolled)
        const unsigned LSB = MU & (0u - MU);
        const unsigned RHO = (unsigned)tb.g[gi].rho;
#pragma unroll
        for (int kk = 0; kk < NITER; kk++) {
            u64 bb   = (u64)(__popc(rep[kk] & (unsigned)tb.g[gi].umask) & 1u);
            u64 bmsk = (0ULL - bb) & SGNC;
            u64 A  = u0, D = u3;
            u64 B0 = u1 ^ bmsk, C0 = u2 ^ bmsk;
            u64 B1 = B0 ^ SGNC, C1 = C0 ^ SGNC;
#pragma unroll
            for (int m = 0; m < NA; m++) {
                if (m & LSB) continue;                   // one member per pair
                const int p = m ^ (int)MU;
                const bool s = (__popc((unsigned)m & RHO) & 1) != 0;   // folds
                u64 Bm = s ? B1 : B0, Cm = s ? C1 : C0;
                u64 Bx = s ? B0 : B1, Cx = s ? C0 : C1;
                u64 a0 = a[kk][m], a1 = a[kk][p];
                u64 a0s = sw64(a0), a1s = sw64(a1);
                a[kk][m] = fma2_(A, a0, fma2_(Bm, a0s, fma2_(Cm, a1, mul2_(D, a1s))));
                a[kk][p] = fma2_(A, a1, fma2_(Bx, a1s, fma2_(Cx, a0, mul2_(D, a0s))));
            }
        }
    }
    if (FINAL) {
        // Direct signed accumulation: per-(m,w) sign popc(m & tw[w]) folds to
        // FADD/FSUB; runtime base sign popc(rep & zu[w]) applied once per w.
        constexpr MeasT mt = make_meas();                // local constexpr: device-safe
#pragma unroll
        for (int kk = 0; kk < NITER; kk++) {
            float sraw[NW];
#pragma unroll
            for (int w = 0; w < NW; w++) sraw[w] = 0.f;
#pragma unroll
            for (int m = 0; m < NA; m++) {
                float ax = __uint_as_float((unsigned)a[kk][m]);
                float ay = __uint_as_float((unsigned)(a[kk][m] >> 32));
                float p = ax * ax + ay * ay;             // a[kk][m] dead after this
#pragma unroll
                for (int w = 0; w < NW; w++) {
                    if (__popc((unsigned)m & (unsigned)mt.tw[w]) & 1) sraw[w] -= p;
                    else                                               sraw[w] += p;
                }
            }
#pragma unroll
            for (int w = 0; w < NW; w++) {
                unsigned bs = (__popc(rep[kk] & (unsigned)mt.zu[w]) & 1u) << 31;
                acc[w] += __uint_as_float(__float_as_uint(sraw[w]) ^ bs);
            }
        }
    } else {
#pragma unroll
        for (int kk = 0; kk < NITER; kk++)
#pragma unroll
            for (int m = 0; m < NA; m++) st[sj[kk] ^ (unsigned)tb.offs[m]] = a[kk][m];
    }
}

template <int SI>
__device__ __forceinline__ void run_all(u64* __restrict__ st, const u64* __restrict__ Us,
                                        const u64* __restrict__ Gs, float* __restrict__ acc) {
    if constexpr (SI < NS) {
        sweepP<SI, (SI == 0), (SI + 1 == NS)>(st, Us, Gs, acc);
        if constexpr (SI + 1 < NS) __syncthreads();
        run_all<SI + 1>(st, Us, Gs, acc);
    }
}

__global__ void __launch_bounds__(NTHREADS, 1)
qsim_kernel(const float* __restrict__ state_batch,
            const float* __restrict__ params,
            const float* __restrict__ head_w,
            const float* __restrict__ head_b,
            float* __restrict__ out) {
    extern __shared__ u64 st[];                    // 16384 x 8B = 128 KB
    __shared__ u64   Usm[2 * NW * 4];              // 28 gates x {u_rr,u_pm,v_rr,v_pm}
    __shared__ u64   Gsm[NW * 4];                  // layer-0 column factors g0,g1 (rr,pm)
    __shared__ float redsm[NWARPS * NW];

    const int b   = blockIdx.x;
    const int tid = threadIdx.x;

    // 28 distinct Rot matrices (weights shared across the 3 blocks).
    // Rot = [[u, v], [-conj(v), conj(u)]]: u = e^{-i(phi+om)/2} cos(th/2),
    // v = -e^{+i(phi-om)/2} sin(th/2).
    if (tid < 2 * NW) {
        const float* p = params + (size_t)b * NPARAMS + tid * 3;
        float phi = p[0], th = p[1], om = p[2];
        float s, c;  sincosf(0.5f * th, &s, &c);
        float sa, ca; sincosf(0.5f * (phi + om), &sa, &ca);
        float sb, cb; sincosf(0.5f * (phi - om), &sb, &cb);
        float ur =  ca * c, ui = -sa * c;
        float vr = -cb * s, vi = -sb * s;
        u64* U = &Usm[tid * 4];
        U[0] = pk( ur, ur);     // u_rr
        U[1] = pk(-ui, ui);     // u_pm
        U[2] = pk( vr, vr);     // v_rr
        U[3] = pk(-vi, vi);     // v_pm
        // Layer-0 column factors for the analytic product state (wires tid<NW,
        // l=0 weights = same param rows).  Column j0_w of U:
        //   j0=0: g0=u00=u,  g1=u10=-conj(v);  j0=1: g0=u01=v, g1=u11=conj(u).
        if (tid < NW) {
            bool j0b = state_batch[(size_t)b * (NSTATE * 2) + tid] < 0.f;
            float g0r, g0i, g1r, g1i;
            if (!j0b) { g0r = ur; g0i = ui; g1r = -vr; g1i = vi; }
            else      { g0r = vr; g0i = vi; g1r = ur;  g1i = -ui; }
            u64* G = &Gsm[tid * 4];
            G[0] = pk( g0r, g0r);
            G[1] = pk(-g0i, g0i);
            G[2] = pk( g1r, g1r);
            G[3] = pk(-g1i, g1i);
        }
    }
    __syncthreads();                                // Usm, Gsm ready

    float acc[NW];
#pragma unroll
    for (int w = 0; w < NW; w++) acc[w] = 0.f;

    run_all<0>(st, Usm, Gsm, acc);

    // Block-reduce acc and apply linear head
#pragma unroll
    for (int w = 0; w < NW; w++) {
#pragma unroll
        for (int o = 16; o > 0; o >>= 1) acc[w] += __shfl_xor_sync(0xffffffffu, acc[w], o);
    }
    const int lane = tid & 31, warp = tid >> 5;
    if (lane == 0) {
#pragma unroll
        for (int w = 0; w < NW; w++) redsm[warp * NW + w] = acc[w];
    }
    __syncthreads();
    if (warp == 0 && lane < NW) {
        float z = 0.f;
#pragma unroll
        for (int k = 0; k < NWARPS; k++) z += redsm[k * NW + lane];
        redsm[lane] = z * head_w[lane];
    }
    __syncthreads();
    if (tid == 0) {
        float r_ = head_b[0];
#pragma unroll
        for (int w = 0; w < NW; w++) r_ += redsm[w];
        out[b] = r_;
    }
}

extern "C" void kernel_launch(void* const* d_in, const int* in_sizes, int n_in,
                              void* d_out, int out_size) {
    const float* state_batch = (const float*)d_in[0];
    const float* params      = (const float*)d_in[1];
    const float* head_w      = (const float*)d_in[2];
    const float* head_b      = (const float*)d_in[3];
    float* out = (float*)d_out;

    int B = in_sizes[0] / (NSTATE * 2);   // 512
    cudaFuncSetAttribute(qsim_kernel, cudaFuncAttributeMaxDynamicSharedMemorySize,
                         NSTATE * (int)sizeof(u64));
    qsim_kernel<<<B, NTHREADS, NSTATE * sizeof(u64)>>>(state_batch, params, head_w, head_b, out);
}